// round 3
// baseline (speedup 1.0000x reference)
#include <cuda_runtime.h>
#include <math.h>

// Problem constants
constexpr int Tv = 2048, Cv = 1024;
constexpr int Mdim = 8 * 2048;   // 16384 rows
constexpr float EPS = 1e-6f;

// Scratch (device globals)
__device__ float g_q0[(size_t)Mdim * Cv];      // 64 MB
__device__ float g_q1[(size_t)Mdim * Cv];      // 64 MB
__device__ float g_v [(size_t)Mdim * Cv];      // 64 MB
__device__ float g_sc[(size_t)Mdim * 128];     // 8 MB (sin|cos)

// ---------------------------------------------------------------------------
// TF32 helpers
// ---------------------------------------------------------------------------
__device__ __forceinline__ unsigned f2tf(float x) {
    unsigned r; asm("cvt.rna.tf32.f32 %0, %1;" : "=r"(r) : "f"(x)); return r;
}
__device__ __forceinline__ void mma_tf32(float d[4], const unsigned a[4], const unsigned b[2]) {
    asm volatile("mma.sync.aligned.m16n8k8.row.col.f32.tf32.tf32.f32 "
        "{%0,%1,%2,%3},{%4,%5,%6,%7},{%8,%9},{%0,%1,%2,%3};"
        : "+f"(d[0]), "+f"(d[1]), "+f"(d[2]), "+f"(d[3])
        : "r"(a[0]), "r"(a[1]), "r"(a[2]), "r"(a[3]), "r"(b[0]), "r"(b[1]));
}

// ---------------------------------------------------------------------------
// Main MMA GEMM: C = A @ B + bias.  BM=128, BN=128, BK=16, 256 thr (8 warps 2x4).
// Fragment-packed SMEM: A [s][mt][lane][4regs] (LDS.128), B [s][nt][lane][2regs].
// NSPLIT: 1 = tf32, 3 = tf32x3 (hi/lo split).
// AMODE 1: A = A .* A2 elementwise.  SMODE 1: split store at col 1024 -> C0/C1.
// ---------------------------------------------------------------------------
template<int NSPLIT, int AMODE, int SMODE>
__global__ void __launch_bounds__(256)
mma_gemm_kernel(const float* __restrict__ A, const float* __restrict__ A2,
                const float* __restrict__ Bm, const float* __restrict__ bias,
                float* __restrict__ C0, float* __restrict__ C1,
                int Ndim, int Kdim)
{
    __shared__ float AsP[2][2048];   // 2 s * 8 mt * 32 lanes * 4 regs
    __shared__ float BsP[2][2048];   // 2 s * 16 nt * 32 lanes * 2 regs

    const int tid = threadIdx.x;
    const int warp = tid >> 5, lane = tid & 31;
    const int bm = blockIdx.y * 128, bn = blockIdx.x * 128;
    const int wmt = (warp >> 2) * 4;   // warp's first m-tile (16 rows each)
    const int wnt = (warp & 3) * 4;    // warp's first n-tile (8 cols each)

    float acc[4][4][4];
#pragma unroll
    for (int i = 0; i < 4; i++)
#pragma unroll
        for (int j = 0; j < 4; j++)
#pragma unroll
            for (int r = 0; r < 4; r++) acc[i][j][r] = 0.f;

    float4 aR[2], bR[2];

    auto gload = [&](int k0) {
#pragma unroll
        for (int l = 0; l < 2; l++) {
            int f = tid + l * 256;
            int m = f >> 2, jq = f & 3;
            size_t gi = (size_t)(bm + m) * Kdim + k0 + 4 * jq;
            float4 av = *reinterpret_cast<const float4*>(&A[gi]);
            if (AMODE == 1) {
                float4 vv = *reinterpret_cast<const float4*>(&A2[gi]);
                av.x *= vv.x; av.y *= vv.y; av.z *= vv.z; av.w *= vv.w;
            }
            aR[l] = av;
            int kr = f >> 5, n0 = (f & 31) * 4;
            bR[l] = *reinterpret_cast<const float4*>(&Bm[(size_t)(k0 + kr) * Ndim + bn + n0]);
        }
    };

    gload(0);
    const int KT = Kdim >> 4;

    for (int kt = 0; kt < KT; kt++) {
        const int buf = kt & 1;
        // fragment-packed STS
#pragma unroll
        for (int l = 0; l < 2; l++) {
            int f = tid + l * 256;
            int m = f >> 2, jq = f & 3;
            int s = jq >> 1, rhi = jq & 1;
            int mt = m >> 4, mm = m & 15, rlo = mm >> 3, gg = mm & 7;
            int r = rlo + 2 * rhi;
            int base = (s * 8 + mt) * 32 + gg * 4;
            AsP[buf][(base + 0) * 4 + r] = aR[l].x;
            AsP[buf][(base + 1) * 4 + r] = aR[l].y;
            AsP[buf][(base + 2) * 4 + r] = aR[l].z;
            AsP[buf][(base + 3) * 4 + r] = aR[l].w;

            int kr = f >> 5, n0 = (f & 31) * 4;
            int s2 = kr >> 3, kk = kr & 7, cc = kk & 3, rb = kk >> 2;
            float bv[4] = {bR[l].x, bR[l].y, bR[l].z, bR[l].w};
#pragma unroll
            for (int e = 0; e < 4; e++) {
                int n = n0 + e, nt = n >> 3, g2 = n & 7;
                BsP[buf][((s2 * 16 + nt) * 32 + g2 * 4 + cc) * 2 + rb] = bv[e];
            }
        }
        __syncthreads();
        if (kt + 1 < KT) gload((kt + 1) * 16);

        // compute
#pragma unroll
        for (int s = 0; s < 2; s++) {
            unsigned ahi[4][4], alo[4][4], bhi[4][2], blo[4][2];
#pragma unroll
            for (int i = 0; i < 4; i++) {
                float4 av = *reinterpret_cast<const float4*>(
                    &AsP[buf][((s * 8 + wmt + i) * 32 + lane) * 4]);
                float af[4] = {av.x, av.y, av.z, av.w};
#pragma unroll
                for (int r = 0; r < 4; r++) {
                    ahi[i][r] = f2tf(af[r]);
                    if (NSPLIT == 3)
                        alo[i][r] = f2tf(af[r] - __uint_as_float(ahi[i][r]));
                }
            }
#pragma unroll
            for (int j = 0; j < 4; j++) {
                float2 bv = *reinterpret_cast<const float2*>(
                    &BsP[buf][((s * 16 + wnt + j) * 32 + lane) * 2]);
                bhi[j][0] = f2tf(bv.x); bhi[j][1] = f2tf(bv.y);
                if (NSPLIT == 3) {
                    blo[j][0] = f2tf(bv.x - __uint_as_float(bhi[j][0]));
                    blo[j][1] = f2tf(bv.y - __uint_as_float(bhi[j][1]));
                }
            }
#pragma unroll
            for (int i = 0; i < 4; i++)
#pragma unroll
                for (int j = 0; j < 4; j++) {
                    if (NSPLIT == 3) {
                        mma_tf32(acc[i][j], alo[i], bhi[j]);
                        mma_tf32(acc[i][j], ahi[i], blo[j]);
                    }
                    mma_tf32(acc[i][j], ahi[i], bhi[j]);
                }
        }
        __syncthreads();
    }

    // epilogue
    const int g = lane >> 2, c = lane & 3;
#pragma unroll
    for (int i = 0; i < 4; i++) {
        int r0 = bm + (wmt + i) * 16 + g;
#pragma unroll
        for (int j = 0; j < 4; j++) {
            int cn = bn + (wnt + j) * 8 + 2 * c;
            float bx = bias[cn], by = bias[cn + 1];
            float2 v0 = make_float2(acc[i][j][0] + bx, acc[i][j][1] + by);
            float2 v1 = make_float2(acc[i][j][2] + bx, acc[i][j][3] + by);
            if (SMODE == 0) {
                *reinterpret_cast<float2*>(&C0[(size_t)r0 * Ndim + cn]) = v0;
                *reinterpret_cast<float2*>(&C0[(size_t)(r0 + 8) * Ndim + cn]) = v1;
            } else {
                float* Ct = (bn < 1024) ? C0 : C1;
                int c2 = cn - ((bn < 1024) ? 0 : 1024);
                *reinterpret_cast<float2*>(&Ct[(size_t)r0 * 1024 + c2]) = v0;
                *reinterpret_cast<float2*>(&Ct[(size_t)(r0 + 8) * 1024 + c2]) = v1;
            }
        }
    }
}

// ---------------------------------------------------------------------------
// Freq GEMM (scan step): f = [prev | q] @ freq_W + freq_b; sc = [sin f | cos f].
// BM=64, BN=64, BK=16, 128 thr (4 warps 2x2, warp tile 32x32). tf32x3.
// ---------------------------------------------------------------------------
template<int NSPLIT>
__global__ void __launch_bounds__(128)
freq_mma_kernel(const float* __restrict__ q, const float* __restrict__ freq_W,
                const float* __restrict__ freq_b, const float* __restrict__ identity,
                float* __restrict__ sc, int n)
{
    __shared__ float AsP[2][1024];   // 2 s * 4 mt * 32 * 4
    __shared__ float BsP[2][1024];   // 2 s * 8 nt * 32 * 2

    const int tid = threadIdx.x;
    const int warp = tid >> 5, lane = tid & 31;
    const int bm = blockIdx.x * 64;
    const int wmt = (warp >> 1) * 2;   // 2 m-tiles per warp
    const int wnt = (warp & 1) * 4;    // 4 n-tiles per warp

    float acc[2][4][4];
#pragma unroll
    for (int i = 0; i < 2; i++)
#pragma unroll
        for (int j = 0; j < 4; j++)
#pragma unroll
            for (int r = 0; r < 4; r++) acc[i][j][r] = 0.f;

    float4 aR[2], bR[2];

    auto gload = [&](int k0) {
#pragma unroll
        for (int l = 0; l < 2; l++) {
            int f = tid + l * 128;
            int m = f >> 2, jq = f & 3;
            int gr = bm + m;
            int kg = k0 + 4 * jq;
            const float* src;
            if (kg < 1024) {
                int t = gr & (Tv - 1);
                src = (t >= n) ? &q[(size_t)(gr - n) * Cv + kg] : &identity[kg];
            } else {
                src = &q[(size_t)gr * Cv + (kg - 1024)];
            }
            aR[l] = *reinterpret_cast<const float4*>(src);
            int kr = f >> 4, n0 = (f & 15) * 4;
            bR[l] = *reinterpret_cast<const float4*>(&freq_W[(size_t)(k0 + kr) * 64 + n0]);
        }
    };

    gload(0);
    const int KT = 2048 >> 4;   // 128

    for (int kt = 0; kt < KT; kt++) {
        const int buf = kt & 1;
#pragma unroll
        for (int l = 0; l < 2; l++) {
            int f = tid + l * 128;
            int m = f >> 2, jq = f & 3;
            int s = jq >> 1, rhi = jq & 1;
            int mt = m >> 4, mm = m & 15, rlo = mm >> 3, gg = mm & 7;
            int r = rlo + 2 * rhi;
            int base = (s * 4 + mt) * 32 + gg * 4;
            AsP[buf][(base + 0) * 4 + r] = aR[l].x;
            AsP[buf][(base + 1) * 4 + r] = aR[l].y;
            AsP[buf][(base + 2) * 4 + r] = aR[l].z;
            AsP[buf][(base + 3) * 4 + r] = aR[l].w;

            int kr = f >> 4, n0 = (f & 15) * 4;
            int s2 = kr >> 3, kk = kr & 7, cc = kk & 3, rb = kk >> 2;
            float bv[4] = {bR[l].x, bR[l].y, bR[l].z, bR[l].w};
#pragma unroll
            for (int e = 0; e < 4; e++) {
                int nn = n0 + e, nt = nn >> 3, g2 = nn & 7;
                BsP[buf][((s2 * 8 + nt) * 32 + g2 * 4 + cc) * 2 + rb] = bv[e];
            }
        }
        __syncthreads();
        if (kt + 1 < KT) gload((kt + 1) * 16);

#pragma unroll
        for (int s = 0; s < 2; s++) {
            unsigned ahi[2][4], alo[2][4], bhi[4][2], blo[4][2];
#pragma unroll
            for (int i = 0; i < 2; i++) {
                float4 av = *reinterpret_cast<const float4*>(
                    &AsP[buf][((s * 4 + wmt + i) * 32 + lane) * 4]);
                float af[4] = {av.x, av.y, av.z, av.w};
#pragma unroll
                for (int r = 0; r < 4; r++) {
                    ahi[i][r] = f2tf(af[r]);
                    if (NSPLIT == 3)
                        alo[i][r] = f2tf(af[r] - __uint_as_float(ahi[i][r]));
                }
            }
#pragma unroll
            for (int j = 0; j < 4; j++) {
                float2 bv = *reinterpret_cast<const float2*>(
                    &BsP[buf][((s * 8 + wnt + j) * 32 + lane) * 2]);
                bhi[j][0] = f2tf(bv.x); bhi[j][1] = f2tf(bv.y);
                if (NSPLIT == 3) {
                    blo[j][0] = f2tf(bv.x - __uint_as_float(bhi[j][0]));
                    blo[j][1] = f2tf(bv.y - __uint_as_float(bhi[j][1]));
                }
            }
#pragma unroll
            for (int i = 0; i < 2; i++)
#pragma unroll
                for (int j = 0; j < 4; j++) {
                    if (NSPLIT == 3) {
                        mma_tf32(acc[i][j], alo[i], bhi[j]);
                        mma_tf32(acc[i][j], ahi[i], blo[j]);
                    }
                    mma_tf32(acc[i][j], ahi[i], bhi[j]);
                }
        }
        __syncthreads();
    }

    // epilogue: sin/cos
    const int g = lane >> 2, c = lane & 3;
#pragma unroll
    for (int i = 0; i < 2; i++) {
        int r0 = bm + (wmt + i) * 16 + g;
#pragma unroll
        for (int j = 0; j < 4; j++) {
            int cn = (wnt + j) * 8 + 2 * c;
            float bx = freq_b[cn], by = freq_b[cn + 1];
            float f0 = acc[i][j][0] + bx, f1 = acc[i][j][1] + by;
            float f2v = acc[i][j][2] + bx, f3v = acc[i][j][3] + by;
            *reinterpret_cast<float2*>(&sc[(size_t)r0 * 128 + cn]) =
                make_float2(sinf(f0), sinf(f1));
            *reinterpret_cast<float2*>(&sc[(size_t)r0 * 128 + 64 + cn]) =
                make_float2(cosf(f0), cosf(f1));
            *reinterpret_cast<float2*>(&sc[(size_t)(r0 + 8) * 128 + cn]) =
                make_float2(sinf(f2v), sinf(f3v));
            *reinterpret_cast<float2*>(&sc[(size_t)(r0 + 8) * 128 + 64 + cn]) =
                make_float2(cosf(f2v), cosf(f3v));
        }
    }
}

// ---------------------------------------------------------------------------
// mmnorm: in-place per-row q /= (max|q| + EPS). Already at memory floor.
// ---------------------------------------------------------------------------
__global__ void __launch_bounds__(256)
mmnorm_kernel(float* __restrict__ q)
{
    int r = blockIdx.x;
    int tid = threadIdx.x;
    float4* row = reinterpret_cast<float4*>(q + (size_t)r * Cv);
    float4 v = row[tid];
    float m = fmaxf(fmaxf(fabsf(v.x), fabsf(v.y)), fmaxf(fabsf(v.z), fabsf(v.w)));
#pragma unroll
    for (int o = 16; o; o >>= 1) m = fmaxf(m, __shfl_xor_sync(0xffffffffu, m, o));
    __shared__ float wm[8];
    if ((tid & 31) == 0) wm[tid >> 5] = m;
    __syncthreads();
    float mm = wm[0];
#pragma unroll
    for (int i = 1; i < 8; i++) mm = fmaxf(mm, wm[i]);
    float inv = 1.0f / (mm + EPS);
    v.x *= inv; v.y *= inv; v.z *= inv; v.w *= inv;
    row[tid] = v;
}

// ---------------------------------------------------------------------------
extern "C" void kernel_launch(void* const* d_in, const int* in_sizes, int n_in,
                              void* d_out, int out_size)
{
    const float* x        = (const float*)d_in[0];
    const float* attn_W   = (const float*)d_in[1];
    const float* attn_b   = (const float*)d_in[2];
    const float* freq_W   = (const float*)d_in[3];
    const float* freq_b   = (const float*)d_in[4];
    const float* out_W    = (const float*)d_in[5];
    const float* out_b    = (const float*)d_in[6];
    const float* proj_W   = (const float*)d_in[7];
    const float* proj_b   = (const float*)d_in[8];
    const float* identity = (const float*)d_in[9];
    float* out = (float*)d_out;

    float *q0, *q1, *v, *sc;
    cudaGetSymbolAddress((void**)&q0, g_q0);
    cudaGetSymbolAddress((void**)&q1, g_q1);
    cudaGetSymbolAddress((void**)&v,  g_v);
    cudaGetSymbolAddress((void**)&sc, g_sc);

    // 1) qv = x @ attn_W + attn_b -> split q | v   (tf32x1)
    {
        dim3 grid(2048 / 128, Mdim / 128);
        mma_gemm_kernel<1, 0, 1><<<grid, 256>>>(x, nullptr, attn_W, attn_b,
                                                q0, v, 2048, Cv);
    }

    // 2) scan (11 iterations), tf32x3 for accuracy
    float* qsrc = q0;
    float* qdst = q1;
    for (int n = 1; n < Tv; n <<= 1) {
        freq_mma_kernel<3><<<Mdim / 64, 128>>>(qsrc, freq_W, freq_b, identity, sc, n);

        dim3 grid(Cv / 128, Mdim / 128);
        mma_gemm_kernel<3, 0, 0><<<grid, 256>>>(sc, nullptr, out_W, out_b,
                                                qdst, nullptr, Cv, 128);

        mmnorm_kernel<<<Mdim, 256>>>(qdst);

        float* tmp = qsrc; qsrc = qdst; qdst = tmp;
    }

    // 3) out = (q .* v) @ proj_W + proj_b   (tf32x1)
    {
        dim3 grid(Cv / 128, Mdim / 128);
        mma_gemm_kernel<1, 1, 0><<<grid, 256>>>(qsrc, v, proj_W, proj_b,
                                                out, nullptr, Cv, Cv);
    }
}

// round 7
// speedup vs baseline: 1.9942x; 1.9942x over previous
#include <cuda_runtime.h>
#include <cuda_bf16.h>
#include <math.h>
#include <stdint.h>

constexpr int Tv = 2048, Cv = 1024, Md = 16384;
constexpr float EPS = 1e-6f;
constexpr int SMEMSZ = 1024 + 65536;   // header + 4 tiles x 16KB

// Arch-specific feature gate: TC_OK=1 only in an sm_103a/f device pass.
#if defined(__CUDA_ARCH_FEAT_SM103_ALL) || defined(__CUDA_ARCH_SPECIFIC__) || defined(__CUDA_ARCH_FAMILY_SPECIFIC__)
#define TC_OK 1
#else
#define TC_OK 0
#endif

// ---------------- device-global scratch ----------------
__device__ float g_q0[(size_t)Md * Cv];
__device__ float g_q1[(size_t)Md * Cv];
__device__ float g_v [(size_t)Md * Cv];
__device__ float g_scf[(size_t)Md * 128];
__device__ __nv_bfloat16 g_qhi[(size_t)Md * Cv], g_qlo[(size_t)Md * Cv];
__device__ __nv_bfloat16 g_xhi[(size_t)Md * Cv], g_xlo[(size_t)Md * Cv];
__device__ __nv_bfloat16 g_schi[(size_t)Md * 128], g_sclo[(size_t)Md * 128];
__device__ __nv_bfloat16 g_aWhi[(size_t)2048 * 1024], g_aWlo[(size_t)2048 * 1024];
__device__ __nv_bfloat16 g_fWhi[(size_t)64 * 2048],   g_fWlo[(size_t)64 * 2048];
__device__ __nv_bfloat16 g_oWhi[(size_t)1024 * 128],  g_oWlo[(size_t)1024 * 128];
__device__ __nv_bfloat16 g_pWhi[(size_t)1024 * 1024], g_pWlo[(size_t)1024 * 1024];
__device__ __nv_bfloat16 g_idhi[1024], g_idlo[1024];

// ---------------- helpers ----------------
__device__ __forceinline__ void split1(float x, __nv_bfloat16& h, __nv_bfloat16& l) {
    h = __float2bfloat16_rn(x);
    l = __float2bfloat16_rn(x - __bfloat162float(h));
}

#if TC_OK
__device__ __forceinline__ uint32_t smem_u32(const void* p) {
    uint32_t a;
    asm("{ .reg .u64 t; cvta.to.shared.u64 t, %1; cvt.u32.u64 %0, t; }" : "=r"(a) : "l"(p));
    return a;
}
__device__ __forceinline__ bool elect1() {
    uint32_t p;
    asm volatile("{\n\t.reg .pred p;\n\telect.sync _|p, 0xFFFFFFFF;\n\tselp.b32 %0,1,0,p;\n\t}" : "=r"(p));
    return p != 0;
}
#define SWZ(o) ((o) ^ (((o) >> 3) & 0x70))
__device__ __forceinline__ uint64_t mkdesc(uint32_t a) {
    const uint64_t base = (uint64_t(2) << 61) | (uint64_t(1) << 46) | (uint64_t(64) << 32) | (uint64_t(1) << 16);
    return base | ((uint64_t)(a >> 4) & 0x3FFF);
}
#define MBAR_INIT(mb, c) asm volatile("mbarrier.init.shared.b64 [%0], %1;" :: "r"(mb), "r"((uint32_t)(c)) : "memory")
#define MBAR_INVAL(mb)   asm volatile("mbarrier.inval.shared.b64 [%0];" :: "r"(mb) : "memory")
__device__ __forceinline__ void mbar_wait(uint32_t mb, uint32_t ph) {
    uint32_t done;
    asm volatile("{\n\t.reg .pred p;\n\tmbarrier.try_wait.parity.acquire.cta.shared::cta.b64 p, [%1], %2;\n\tselp.b32 %0,1,0,p;\n\t}"
                 : "=r"(done) : "r"(mb), "r"(ph) : "memory");
    if (!done)
        asm volatile("{\n\t.reg .pred P1;\nWL_%=:\n\tmbarrier.try_wait.parity.acquire.cta.shared::cta.b64 P1, [%0], %1, 0x989680;\n\t@P1 bra.uni WD_%=;\n\tbra.uni WL_%=;\nWD_%=:\n\t}"
                     :: "r"(mb), "r"(ph) : "memory");
}
#define TC_ALLOC(sm, n)  asm volatile("tcgen05.alloc.cta_group::1.sync.aligned.shared::cta.b32 [%0], %1;" :: "r"(sm), "r"((uint32_t)(n)) : "memory")
#define TC_DEALLOC(t, n) asm volatile("tcgen05.dealloc.cta_group::1.sync.aligned.b32 %0, %1;" :: "r"(t), "r"((uint32_t)(n)))
#define TC_RELINQ()      asm volatile("tcgen05.relinquish_alloc_permit.cta_group::1.sync.aligned;")
#define TC_COMMIT(mb)    asm volatile("tcgen05.commit.cta_group::1.mbarrier::arrive::one.shared::cluster.b64 [%0];" :: "r"(mb) : "memory")
#define TC_FENCE_AFTER() asm volatile("tcgen05.fence::after_thread_sync;" ::: "memory")
#define TC_WAIT_LD()     asm volatile("tcgen05.wait::ld.sync.aligned;" ::: "memory")
#define FENCE_ASYNC()    asm volatile("fence.proxy.async.shared::cta;" ::: "memory")
__device__ __forceinline__ void tc_mma(uint32_t d, uint64_t ad, uint64_t bd, uint32_t idesc, uint32_t en) {
    asm volatile("{\n\t.reg .pred p;\n\tsetp.ne.u32 p, %5, 0;\n\t"
                 "tcgen05.mma.cta_group::1.kind::f16 [%0], %1, %2, %3, {%4,%4,%4,%4}, p;\n\t}"
                 :: "r"(d), "l"(ad), "l"(bd), "r"(idesc), "r"(0u), "r"(en) : "memory");
}
#define TC_LD_X32(r, tm) \
    asm volatile("tcgen05.ld.sync.aligned.32x32b.x32.b32 " \
        "{%0,%1,%2,%3,%4,%5,%6,%7,%8,%9,%10,%11,%12,%13,%14,%15," \
        "%16,%17,%18,%19,%20,%21,%22,%23,%24,%25,%26,%27,%28,%29,%30,%31}, [%32];" \
        : "=r"((r)[0]),"=r"((r)[1]),"=r"((r)[2]),"=r"((r)[3]),"=r"((r)[4]),"=r"((r)[5]),"=r"((r)[6]),"=r"((r)[7]), \
          "=r"((r)[8]),"=r"((r)[9]),"=r"((r)[10]),"=r"((r)[11]),"=r"((r)[12]),"=r"((r)[13]),"=r"((r)[14]),"=r"((r)[15]), \
          "=r"((r)[16]),"=r"((r)[17]),"=r"((r)[18]),"=r"((r)[19]),"=r"((r)[20]),"=r"((r)[21]),"=r"((r)[22]),"=r"((r)[23]), \
          "=r"((r)[24]),"=r"((r)[25]),"=r"((r)[26]),"=r"((r)[27]),"=r"((r)[28]),"=r"((r)[29]),"=r"((r)[30]),"=r"((r)[31]) \
        : "r"(tm))
// Verified idesc family (test_mma.cu: M=128,N=32 -> 0x8080490)
constexpr uint32_t IDESC128 = 0x8200490u;   // M=128, N=128
constexpr uint32_t IDESC64  = 0x8100490u;   // M=128, N=64
#endif  // TC_OK

// ============================ tcgen05 path ============================
__global__ void tsplit_kernel(const float* __restrict__ W, __nv_bfloat16* __restrict__ hi,
                              __nv_bfloat16* __restrict__ lo, int K, int N) {
#if TC_OK
    size_t i = (size_t)blockIdx.x * 256 + threadIdx.x;
    if (i >= (size_t)K * N) return;
    int n = (int)(i / K), k = (int)(i % K);
    split1(W[(size_t)k * N + n], hi[i], lo[i]);
#endif
}
__global__ void splitx_kernel(const float* __restrict__ X, __nv_bfloat16* __restrict__ hi,
                              __nv_bfloat16* __restrict__ lo, size_t n4) {
#if TC_OK
    size_t i = (size_t)blockIdx.x * 256 + threadIdx.x;
    if (i >= n4) return;
    float4 x = reinterpret_cast<const float4*>(X)[i];
    __nv_bfloat16 h[4], l[4];
    split1(x.x, h[0], l[0]); split1(x.y, h[1], l[1]);
    split1(x.z, h[2], l[2]); split1(x.w, h[3], l[3]);
    reinterpret_cast<__nv_bfloat162*>(hi)[2 * i]     = __nv_bfloat162{h[0], h[1]};
    reinterpret_cast<__nv_bfloat162*>(hi)[2 * i + 1] = __nv_bfloat162{h[2], h[3]};
    reinterpret_cast<__nv_bfloat162*>(lo)[2 * i]     = __nv_bfloat162{l[0], l[1]};
    reinterpret_cast<__nv_bfloat162*>(lo)[2 * i + 1] = __nv_bfloat162{l[2], l[3]};
#endif
}
template<int MULV>
__global__ void __launch_bounds__(256)
normsplit_kernel(const float* __restrict__ z, const float* __restrict__ v,
                 __nv_bfloat16* __restrict__ hi, __nv_bfloat16* __restrict__ lo) {
#if TC_OK
    int r = blockIdx.x, tid = threadIdx.x;
    float4 x = reinterpret_cast<const float4*>(z + (size_t)r * Cv)[tid];
    float m = fmaxf(fmaxf(fabsf(x.x), fabsf(x.y)), fmaxf(fabsf(x.z), fabsf(x.w)));
#pragma unroll
    for (int o = 16; o; o >>= 1) m = fmaxf(m, __shfl_xor_sync(~0u, m, o));
    __shared__ float wm[8];
    if ((tid & 31) == 0) wm[tid >> 5] = m;
    __syncthreads();
    float mm = wm[0];
#pragma unroll
    for (int i = 1; i < 8; i++) mm = fmaxf(mm, wm[i]);
    float s = 1.f / (mm + EPS);
    float4 y = make_float4(x.x * s, x.y * s, x.z * s, x.w * s);
    if (MULV) {
        float4 vv = reinterpret_cast<const float4*>(v + (size_t)r * Cv)[tid];
        y.x *= vv.x; y.y *= vv.y; y.z *= vv.z; y.w *= vv.w;
    }
    __nv_bfloat16 h[4], l[4];
    split1(y.x, h[0], l[0]); split1(y.y, h[1], l[1]);
    split1(y.z, h[2], l[2]); split1(y.w, h[3], l[3]);
    size_t o2 = (size_t)r * (Cv / 2) + 2 * tid;
    reinterpret_cast<__nv_bfloat162*>(hi)[o2]     = __nv_bfloat162{h[0], h[1]};
    reinterpret_cast<__nv_bfloat162*>(hi)[o2 + 1] = __nv_bfloat162{h[2], h[3]};
    reinterpret_cast<__nv_bfloat162*>(lo)[o2]     = __nv_bfloat162{l[0], l[1]};
    reinterpret_cast<__nv_bfloat162*>(lo)[o2 + 1] = __nv_bfloat162{l[2], l[3]};
#endif
}

// EPI 0: attn  EPI 1: freq(sincos)  EPI 2: plain +bias fp32
// Single SMEM buffer, commit+wait per K-tile (example-faithful flow).
template<int EPI>
__global__ void __launch_bounds__(256) __cluster_dims__(1, 1, 1)
tc_gemm(const __nv_bfloat16* __restrict__ Ahi, const __nv_bfloat16* __restrict__ Alo,
        const __nv_bfloat16* __restrict__ Bhi, const __nv_bfloat16* __restrict__ Blo,
        const float* __restrict__ bias, float* __restrict__ C, int ldc, int Kdim,
        __nv_bfloat16* __restrict__ OH, __nv_bfloat16* __restrict__ OL,
        float* __restrict__ Vout, int nshift)
{
#if TC_OK
    extern __shared__ char sm[];
    const uint32_t sb = smem_u32(sm);
    const int tid = threadIdx.x, wid = tid >> 5, lane = tid & 31;
    const int bm = blockIdx.y * 128, bn = blockIdx.x * ((EPI == 1) ? 64 : 128);
    const int NT = (EPI == 1) ? 64 : 128;
    const uint32_t idesc = (EPI == 1) ? IDESC64 : IDESC128;
    const int KT = Kdim >> 6;

    if (wid == 0) TC_ALLOC(sb + 0, 256);
    if (tid == 0) MBAR_INIT(sb + 8, 1);
    __syncthreads();
    uint32_t tmem;
    asm volatile("ld.shared.b32 %0, [%1];" : "=r"(tmem) : "r"(sb + 0));

    const int arow = tid >> 1, ah = tid & 1;
    char* tb = sm + 1024;

#pragma unroll 1
    for (int kt = 0; kt < KT; kt++) {
        const int k0 = kt * 64;
        // ---- A tile (hi at +0, lo at +16384) ----
        {
            const __nv_bfloat16 *sh, *sl;
            if (EPI == 1) {
                int r = bm + arow, t = r & (Tv - 1);
                if (k0 < 1024) {
                    int kg = k0 + 32 * ah;
                    if (t >= nshift) { sh = Ahi + (size_t)(r - nshift) * Cv + kg; sl = Alo + (size_t)(r - nshift) * Cv + kg; }
                    else             { sh = g_idhi + kg; sl = g_idlo + kg; }
                } else {
                    int kg = k0 - 1024 + 32 * ah;
                    sh = Ahi + (size_t)r * Cv + kg; sl = Alo + (size_t)r * Cv + kg;
                }
            } else {
                sh = Ahi + (size_t)(bm + arow) * Kdim + k0 + 32 * ah;
                sl = Alo + (size_t)(bm + arow) * Kdim + k0 + 32 * ah;
            }
#pragma unroll
            for (int j = 0; j < 4; j++) {
                int off = arow * 128 + (32 * ah + 8 * j) * 2;
                *reinterpret_cast<uint4*>(tb + SWZ(off))         = reinterpret_cast<const uint4*>(sh)[j];
                *reinterpret_cast<uint4*>(tb + 16384 + SWZ(off)) = reinterpret_cast<const uint4*>(sl)[j];
            }
        }
        // ---- B tile (hi at +32768, lo at +49152) ----
        for (int it = tid; it < NT * 2; it += 256) {
            int row = it >> 1, h = it & 1;
            const __nv_bfloat16* bh = Bhi + (size_t)(bn + row) * Kdim + k0 + 32 * h;
            const __nv_bfloat16* bl = Blo + (size_t)(bn + row) * Kdim + k0 + 32 * h;
#pragma unroll
            for (int j = 0; j < 4; j++) {
                int off = row * 128 + (32 * h + 8 * j) * 2;
                *reinterpret_cast<uint4*>(tb + 32768 + SWZ(off)) = reinterpret_cast<const uint4*>(bh)[j];
                *reinterpret_cast<uint4*>(tb + 49152 + SWZ(off)) = reinterpret_cast<const uint4*>(bl)[j];
            }
        }
        FENCE_ASYNC();
        __syncthreads();
        if (wid == 0 && elect1()) {
            uint32_t base = sb + 1024;
            uint64_t dAh = mkdesc(base), dAl = mkdesc(base + 16384);
            uint64_t dBh = mkdesc(base + 32768), dBl = mkdesc(base + 49152);
#pragma unroll
            for (int s = 0; s < 4; s++) {
                tc_mma(tmem, dAh + 2 * s, dBh + 2 * s, idesc, (kt == 0 && s == 0) ? 0u : 1u);
                tc_mma(tmem, dAh + 2 * s, dBl + 2 * s, idesc, 1u);
                tc_mma(tmem, dAl + 2 * s, dBh + 2 * s, idesc, 1u);
            }
            TC_COMMIT(sb + 8);
        }
        mbar_wait(sb + 8, kt & 1);
        __syncthreads();
    }
    TC_FENCE_AFTER();

    if (wid < 4) {
        const int r = bm + wid * 32 + lane;
        if (EPI == 1) {
            float f[64];
#pragma unroll
            for (int c4 = 0; c4 < 2; c4++) {
                uint32_t regs[32];
                TC_LD_X32(regs, tmem + 32 * c4);
                TC_WAIT_LD();
#pragma unroll
                for (int e = 0; e < 32; e++) f[32 * c4 + e] = __uint_as_float(regs[e]);
            }
#pragma unroll
            for (int e = 0; e < 32; e++) {
                float s0, c0, s1, c1;
                sincosf(f[2 * e]     + bias[2 * e],     &s0, &c0);
                sincosf(f[2 * e + 1] + bias[2 * e + 1], &s1, &c1);
                __nv_bfloat16 h0, l0, h1, l1, h2, l2, h3, l3;
                split1(s0, h0, l0); split1(s1, h1, l1);
                split1(c0, h2, l2); split1(c1, h3, l3);
                size_t os = (size_t)r * 64 + e, oc = os + 32;
                reinterpret_cast<__nv_bfloat162*>(OH)[os] = __nv_bfloat162{h0, h1};
                reinterpret_cast<__nv_bfloat162*>(OL)[os] = __nv_bfloat162{l0, l1};
                reinterpret_cast<__nv_bfloat162*>(OH)[oc] = __nv_bfloat162{h2, h3};
                reinterpret_cast<__nv_bfloat162*>(OL)[oc] = __nv_bfloat162{l2, l3};
            }
        } else {
#pragma unroll 1
            for (int c4 = 0; c4 < 4; c4++) {
                uint32_t regs[32];
                TC_LD_X32(regs, tmem + 32 * c4);
                TC_WAIT_LD();
                const int col0 = bn + 32 * c4;
                if (EPI == 0 && bn < 1024) {
#pragma unroll
                    for (int e = 0; e < 16; e++) {
                        float v0 = __uint_as_float(regs[2 * e])     + bias[col0 + 2 * e];
                        float v1 = __uint_as_float(regs[2 * e + 1]) + bias[col0 + 2 * e + 1];
                        __nv_bfloat16 h0, l0, h1, l1;
                        split1(v0, h0, l0); split1(v1, h1, l1);
                        size_t o2 = (size_t)r * 512 + (col0 >> 1) + e;
                        reinterpret_cast<__nv_bfloat162*>(OH)[o2] = __nv_bfloat162{h0, h1};
                        reinterpret_cast<__nv_bfloat162*>(OL)[o2] = __nv_bfloat162{l0, l1};
                    }
                } else {
                    float* dst = (EPI == 0) ? Vout : C;
                    int cc = (EPI == 0) ? col0 - 1024 : col0;
#pragma unroll
                    for (int e = 0; e < 8; e++) {
                        float4 o;
                        o.x = __uint_as_float(regs[4 * e + 0]) + bias[col0 + 4 * e + 0];
                        o.y = __uint_as_float(regs[4 * e + 1]) + bias[col0 + 4 * e + 1];
                        o.z = __uint_as_float(regs[4 * e + 2]) + bias[col0 + 4 * e + 2];
                        o.w = __uint_as_float(regs[4 * e + 3]) + bias[col0 + 4 * e + 3];
                        *reinterpret_cast<float4*>(dst + (size_t)r * ldc + cc + 4 * e) = o;
                    }
                }
            }
        }
    }
    __syncthreads();
    if (tid == 0) MBAR_INVAL(sb + 8);
    __syncthreads();
    if (wid == 0) { TC_RELINQ(); TC_DEALLOC(tmem, 256); }
#endif  // TC_OK
}

// ============================ FFMA fallback path (R1, proven) ============================
template<int AMODE, int SMODE>
__global__ void __launch_bounds__(256)
gemm128_kernel(const float* __restrict__ A, const float* __restrict__ A2,
               const float* __restrict__ Bm, const float* __restrict__ bias,
               float* __restrict__ C0, float* __restrict__ C1,
               int Ndim, int Kdim)
{
#if !TC_OK
    __shared__ float As[16][128];
    __shared__ float Bs[16][128];
    const int bm = blockIdx.y * 128, bn = blockIdx.x * 128;
    const int tid = threadIdx.x;
    const int tr = tid >> 4, tc = tid & 15;
    float acc[8][8];
#pragma unroll
    for (int i = 0; i < 8; i++)
#pragma unroll
        for (int j = 0; j < 8; j++) acc[i][j] = 0.f;

    for (int k0 = 0; k0 < Kdim; k0 += 16) {
#pragma unroll
        for (int l = 0; l < 2; l++) {
            int f = tid + l * 256;
            int row = f >> 2, kq = (f & 3) * 4;
            size_t gidx = (size_t)(bm + row) * Kdim + k0 + kq;
            float4 av = *reinterpret_cast<const float4*>(&A[gidx]);
            if (AMODE == 1) {
                float4 vv = *reinterpret_cast<const float4*>(&A2[gidx]);
                av.x *= vv.x; av.y *= vv.y; av.z *= vv.z; av.w *= vv.w;
            }
            As[kq + 0][row] = av.x; As[kq + 1][row] = av.y;
            As[kq + 2][row] = av.z; As[kq + 3][row] = av.w;
        }
#pragma unroll
        for (int l = 0; l < 2; l++) {
            int f = tid + l * 256;
            int row = f >> 5, nq = (f & 31) * 4;
            float4 bv = *reinterpret_cast<const float4*>(&Bm[(size_t)(k0 + row) * Ndim + bn + nq]);
            *reinterpret_cast<float4*>(&Bs[row][nq]) = bv;
        }
        __syncthreads();
#pragma unroll
        for (int k = 0; k < 16; k++) {
            float af[8], bf[8];
#pragma unroll
            for (int i = 0; i < 8; i++) af[i] = As[k][tr * 8 + i];
#pragma unroll
            for (int j = 0; j < 8; j++) bf[j] = Bs[k][tc * 8 + j];
#pragma unroll
            for (int i = 0; i < 8; i++)
#pragma unroll
                for (int j = 0; j < 8; j++) acc[i][j] += af[i] * bf[j];
        }
        __syncthreads();
    }
#pragma unroll
    for (int i = 0; i < 8; i++) {
        int r = bm + tr * 8 + i;
#pragma unroll
        for (int j = 0; j < 8; j += 4) {
            int c = bn + tc * 8 + j;
            float4 o;
            o.x = acc[i][j + 0] + bias[c + 0]; o.y = acc[i][j + 1] + bias[c + 1];
            o.z = acc[i][j + 2] + bias[c + 2]; o.w = acc[i][j + 3] + bias[c + 3];
            if (SMODE == 0) {
                *reinterpret_cast<float4*>(&C0[(size_t)r * Ndim + c]) = o;
            } else {
                if (c < 1024) *reinterpret_cast<float4*>(&C0[(size_t)r * 1024 + c]) = o;
                else          *reinterpret_cast<float4*>(&C1[(size_t)r * 1024 + (c - 1024)]) = o;
            }
        }
    }
#endif
}

__global__ void __launch_bounds__(128)
gemm_freq_kernel(const float* __restrict__ q, const float* __restrict__ freq_W,
                 const float* __restrict__ freq_b, const float* __restrict__ identity,
                 float* __restrict__ sc, int n)
{
#if !TC_OK
    __shared__ float As[16][128];
    __shared__ float Bs[16][64];
    const int bm = blockIdx.x * 128;
    const int tid = threadIdx.x;
    const int tr = tid >> 3, tc = tid & 7;
    float acc[8][8];
#pragma unroll
    for (int i = 0; i < 8; i++)
#pragma unroll
        for (int j = 0; j < 8; j++) acc[i][j] = 0.f;

    for (int k0 = 0; k0 < 2048; k0 += 16) {
#pragma unroll
        for (int l = 0; l < 4; l++) {
            int f = tid + l * 128;
            int row = f >> 2, kq = (f & 3) * 4;
            int gr = bm + row;
            float4 av;
            if (k0 < 1024) {
                int t = gr & (Tv - 1);
                if (t >= n) av = *reinterpret_cast<const float4*>(&q[(size_t)(gr - n) * Cv + k0 + kq]);
                else        av = *reinterpret_cast<const float4*>(&identity[k0 + kq]);
            } else {
                av = *reinterpret_cast<const float4*>(&q[(size_t)gr * Cv + (k0 - 1024) + kq]);
            }
            As[kq + 0][row] = av.x; As[kq + 1][row] = av.y;
            As[kq + 2][row] = av.z; As[kq + 3][row] = av.w;
        }
#pragma unroll
        for (int l = 0; l < 2; l++) {
            int f = tid + l * 128;
            int row = f >> 4, nq = (f & 15) * 4;
            float4 bv = *reinterpret_cast<const float4*>(&freq_W[(size_t)(k0 + row) * 64 + nq]);
            *reinterpret_cast<float4*>(&Bs[row][nq]) = bv;
        }
        __syncthreads();
#pragma unroll
        for (int k = 0; k < 16; k++) {
            float af[8], bf[8];
#pragma unroll
            for (int i = 0; i < 8; i++) af[i] = As[k][tr * 8 + i];
#pragma unroll
            for (int j = 0; j < 8; j++) bf[j] = Bs[k][tc * 8 + j];
#pragma unroll
            for (int i = 0; i < 8; i++)
#pragma unroll
                for (int j = 0; j < 8; j++) acc[i][j] += af[i] * bf[j];
        }
        __syncthreads();
    }
#pragma unroll
    for (int i = 0; i < 8; i++) {
        int r = bm + tr * 8 + i;
#pragma unroll
        for (int j = 0; j < 8; j++) {
            int c = tc * 8 + j;
            float fv = acc[i][j] + freq_b[c];
            sc[(size_t)r * 128 + c]      = sinf(fv);
            sc[(size_t)r * 128 + 64 + c] = cosf(fv);
        }
    }
#endif
}

__global__ void __launch_bounds__(256)
mmnorm_kernel(float* __restrict__ q)
{
#if !TC_OK
    int r = blockIdx.x, tid = threadIdx.x;
    float4* row = reinterpret_cast<float4*>(q + (size_t)r * Cv);
    float4 v = row[tid];
    float m = fmaxf(fmaxf(fabsf(v.x), fabsf(v.y)), fmaxf(fabsf(v.z), fabsf(v.w)));
#pragma unroll
    for (int o = 16; o; o >>= 1) m = fmaxf(m, __shfl_xor_sync(0xffffffffu, m, o));
    __shared__ float wm[8];
    if ((tid & 31) == 0) wm[tid >> 5] = m;
    __syncthreads();
    float mm = wm[0];
#pragma unroll
    for (int i = 1; i < 8; i++) mm = fmaxf(mm, wm[i]);
    float inv = 1.0f / (mm + EPS);
    v.x *= inv; v.y *= inv; v.z *= inv; v.w *= inv;
    row[tid] = v;
#endif
}

// ============================ host ============================
extern "C" void kernel_launch(void* const* d_in, const int* in_sizes, int n_in,
                              void* d_out, int out_size)
{
    const float* x        = (const float*)d_in[0];
    const float* attn_W   = (const float*)d_in[1];
    const float* attn_b   = (const float*)d_in[2];
    const float* freq_W   = (const float*)d_in[3];
    const float* freq_b   = (const float*)d_in[4];
    const float* out_W    = (const float*)d_in[5];
    const float* out_b    = (const float*)d_in[6];
    const float* proj_W   = (const float*)d_in[7];
    const float* proj_b   = (const float*)d_in[8];
    const float* identity = (const float*)d_in[9];
    float* out = (float*)d_out;

    cudaFuncSetAttribute(tc_gemm<0>, cudaFuncAttributeMaxDynamicSharedMemorySize, SMEMSZ);
    cudaFuncSetAttribute(tc_gemm<1>, cudaFuncAttributeMaxDynamicSharedMemorySize, SMEMSZ);
    cudaFuncSetAttribute(tc_gemm<2>, cudaFuncAttributeMaxDynamicSharedMemorySize, SMEMSZ);

    float *q0, *q1, *v, *scf;
    cudaGetSymbolAddress((void**)&q0, g_q0);
    cudaGetSymbolAddress((void**)&q1, g_q1);
    cudaGetSymbolAddress((void**)&v,  g_v);
    cudaGetSymbolAddress((void**)&scf, g_scf);
    __nv_bfloat16 *qhi, *qlo, *xhi, *xlo, *schi, *sclo, *aWhi, *aWlo, *fWhi, *fWlo,
                  *oWhi, *oWlo, *pWhi, *pWlo, *idhi, *idlo;
    cudaGetSymbolAddress((void**)&qhi, g_qhi);  cudaGetSymbolAddress((void**)&qlo, g_qlo);
    cudaGetSymbolAddress((void**)&xhi, g_xhi);  cudaGetSymbolAddress((void**)&xlo, g_xlo);
    cudaGetSymbolAddress((void**)&schi, g_schi); cudaGetSymbolAddress((void**)&sclo, g_sclo);
    cudaGetSymbolAddress((void**)&aWhi, g_aWhi); cudaGetSymbolAddress((void**)&aWlo, g_aWlo);
    cudaGetSymbolAddress((void**)&fWhi, g_fWhi); cudaGetSymbolAddress((void**)&fWlo, g_fWlo);
    cudaGetSymbolAddress((void**)&oWhi, g_oWhi); cudaGetSymbolAddress((void**)&oWlo, g_oWlo);
    cudaGetSymbolAddress((void**)&pWhi, g_pWhi); cudaGetSymbolAddress((void**)&pWlo, g_pWlo);
    cudaGetSymbolAddress((void**)&idhi, g_idhi); cudaGetSymbolAddress((void**)&idlo, g_idlo);
    float* z = q1;   // tc path fp32 scratch (fallback kernels are stubs in tc build)

    // ---- tc prep (stubs in fallback build) ----
    tsplit_kernel<<<(1024 * 2048 + 255) / 256, 256>>>(attn_W, aWhi, aWlo, 1024, 2048);
    tsplit_kernel<<<(2048 * 64 + 255) / 256, 256>>>(freq_W, fWhi, fWlo, 2048, 64);
    tsplit_kernel<<<(128 * 1024 + 255) / 256, 256>>>(out_W, oWhi, oWlo, 128, 1024);
    tsplit_kernel<<<(1024 * 1024 + 255) / 256, 256>>>(proj_W, pWhi, pWlo, 1024, 1024);
    tsplit_kernel<<<(1024 + 255) / 256, 256>>>(identity, idhi, idlo, 1, 1024);
    splitx_kernel<<<((size_t)Md * Cv / 4 + 255) / 256, 256>>>(x, xhi, xlo, (size_t)Md * Cv / 4);

    // ---- attn ----
    {
        dim3 grid(16, 128);
        gemm128_kernel<0, 1><<<grid, 256>>>(x, nullptr, attn_W, attn_b, q0, v, 2048, Cv);
        // FIX (R7): ldc=1024 — was 0, which collapsed all v rows onto row 0.
        tc_gemm<0><<<grid, 256, SMEMSZ>>>(xhi, xlo, aWhi, aWlo, attn_b,
                                          nullptr, 1024, 1024, qhi, qlo, v, 0);
    }

    // ---- scan ----
    float* qsrc = q0;
    float* qdst = q1;
    for (int n = 1; n < Tv; n <<= 1) {
        gemm_freq_kernel<<<Md / 128, 128>>>(qsrc, freq_W, freq_b, identity, scf, n);
        {
            dim3 grid(8, 128);
            gemm128_kernel<0, 0><<<grid, 256>>>(scf, nullptr, out_W, out_b, qdst, nullptr, Cv, 128);
        }
        mmnorm_kernel<<<Md, 256>>>(qdst);

        tc_gemm<1><<<dim3(1, 128), 256, SMEMSZ>>>(qhi, qlo, fWhi, fWlo, freq_b,
                                                  nullptr, 0, 2048, schi, sclo, nullptr, n);
        tc_gemm<2><<<dim3(8, 128), 256, SMEMSZ>>>(schi, sclo, oWhi, oWlo, out_b,
                                                  z, 1024, 128, nullptr, nullptr, nullptr, 0);
        if (n * 2 < Tv) normsplit_kernel<0><<<Md, 256>>>(z, nullptr, qhi, qlo);
        else            normsplit_kernel<1><<<Md, 256>>>(z, v, qhi, qlo);

        float* tmp = qsrc; qsrc = qdst; qdst = tmp;
    }

    // ---- proj ----
    {
        dim3 grid(8, 128);
        gemm128_kernel<1, 0><<<grid, 256>>>(qsrc, v, proj_W, proj_b, out, nullptr, Cv, Cv);
        tc_gemm<2><<<grid, 256, SMEMSZ>>>(qhi, qlo, pWhi, pWlo, proj_b,
                                          out, 1024, 1024, nullptr, nullptr, nullptr, 0);
    }
}

// round 8
// speedup vs baseline: 2.1150x; 1.0606x over previous
#include <cuda_runtime.h>
#include <cuda_bf16.h>
#include <math.h>
#include <stdint.h>

constexpr int Tv = 2048, Cv = 1024, Md = 16384;
constexpr float EPS = 1e-6f;
constexpr int SMEMSZ = 1024 + 2 * 65536;   // header + 2 bufs x 4 tiles x 16KB

// Arch-specific feature gate: TC bodies only exist in the sm_103a/f pass.
#if defined(__CUDA_ARCH_FEAT_SM103_ALL) || defined(__CUDA_ARCH_SPECIFIC__) || defined(__CUDA_ARCH_FAMILY_SPECIFIC__)
#define TC_OK 1
#else
#define TC_OK 0
#endif

// ---------------- device-global scratch ----------------
__device__ float g_z0[(size_t)Md * Cv];                 // fp32 q / z ping
__device__ float g_z1[(size_t)Md * Cv];                 // fp32 z pong
__device__ float g_v [(size_t)Md * Cv];                 // fp32 v
__device__ float g_gmax[11 * Md];                       // per-iter row max|z|
__device__ __nv_bfloat16 g_schi[(size_t)Md * 128], g_sclo[(size_t)Md * 128];
__device__ __nv_bfloat16 g_aWhi[(size_t)2048 * 1024], g_aWlo[(size_t)2048 * 1024];
__device__ __nv_bfloat16 g_fWhi[(size_t)64 * 2048],   g_fWlo[(size_t)64 * 2048];
__device__ __nv_bfloat16 g_oWhi[(size_t)1024 * 128],  g_oWlo[(size_t)1024 * 128];
__device__ __nv_bfloat16 g_pWhi[(size_t)1024 * 1024], g_pWlo[(size_t)1024 * 1024];

// ---------------- helpers ----------------
__device__ __forceinline__ void split1(float x, __nv_bfloat16& h, __nv_bfloat16& l) {
    h = __float2bfloat16_rn(x);
    l = __float2bfloat16_rn(x - __bfloat162float(h));
}
__device__ __forceinline__ uint32_t packbf(__nv_bfloat16 a, __nv_bfloat16 b) {
    return (uint32_t)__bfloat16_as_ushort(a) | ((uint32_t)__bfloat16_as_ushort(b) << 16);
}

// transpose+split weights [K,N] -> hi/lo [N,K]
__global__ void tsplit_kernel(const float* __restrict__ W, __nv_bfloat16* __restrict__ hi,
                              __nv_bfloat16* __restrict__ lo, int K, int N) {
    size_t i = (size_t)blockIdx.x * 256 + threadIdx.x;
    if (i >= (size_t)K * N) return;
    int n = (int)(i / K), k = (int)(i % K);
    split1(W[(size_t)k * N + n], hi[i], lo[i]);
}
__global__ void zero_gmax_kernel() {
    int i = blockIdx.x * 1024 + threadIdx.x;
    if (i < 11 * Md) g_gmax[i] = 0.f;
}

#if TC_OK
__device__ __forceinline__ uint32_t smem_u32(const void* p) {
    uint32_t a;
    asm("{ .reg .u64 t; cvta.to.shared.u64 t, %1; cvt.u32.u64 %0, t; }" : "=r"(a) : "l"(p));
    return a;
}
__device__ __forceinline__ bool elect1() {
    uint32_t p;
    asm volatile("{\n\t.reg .pred p;\n\telect.sync _|p, 0xFFFFFFFF;\n\tselp.b32 %0,1,0,p;\n\t}" : "=r"(p));
    return p != 0;
}
#define SWZ(o) ((o) ^ (((o) >> 3) & 0x70))
__device__ __forceinline__ uint64_t mkdesc(uint32_t a) {
    const uint64_t base = (uint64_t(2) << 61) | (uint64_t(1) << 46) | (uint64_t(64) << 32) | (uint64_t(1) << 16);
    return base | ((uint64_t)(a >> 4) & 0x3FFF);
}
#define MBAR_INIT(mb, c) asm volatile("mbarrier.init.shared.b64 [%0], %1;" :: "r"(mb), "r"((uint32_t)(c)) : "memory")
#define MBAR_INVAL(mb)   asm volatile("mbarrier.inval.shared.b64 [%0];" :: "r"(mb) : "memory")
__device__ __forceinline__ void mbar_wait(uint32_t mb, uint32_t ph) {
    uint32_t done;
    asm volatile("{\n\t.reg .pred p;\n\tmbarrier.try_wait.parity.acquire.cta.shared::cta.b64 p, [%1], %2;\n\tselp.b32 %0,1,0,p;\n\t}"
                 : "=r"(done) : "r"(mb), "r"(ph) : "memory");
    if (!done)
        asm volatile("{\n\t.reg .pred P1;\nWL_%=:\n\tmbarrier.try_wait.parity.acquire.cta.shared::cta.b64 P1, [%0], %1, 0x989680;\n\t@P1 bra.uni WD_%=;\n\tbra.uni WL_%=;\nWD_%=:\n\t}"
                     :: "r"(mb), "r"(ph) : "memory");
}
#define TC_ALLOC(sm, n)  asm volatile("tcgen05.alloc.cta_group::1.sync.aligned.shared::cta.b32 [%0], %1;" :: "r"(sm), "r"((uint32_t)(n)) : "memory")
#define TC_DEALLOC(t, n) asm volatile("tcgen05.dealloc.cta_group::1.sync.aligned.b32 %0, %1;" :: "r"(t), "r"((uint32_t)(n)))
#define TC_RELINQ()      asm volatile("tcgen05.relinquish_alloc_permit.cta_group::1.sync.aligned;")
#define TC_COMMIT(mb)    asm volatile("tcgen05.commit.cta_group::1.mbarrier::arrive::one.shared::cluster.b64 [%0];" :: "r"(mb) : "memory")
#define TC_FENCE_AFTER() asm volatile("tcgen05.fence::after_thread_sync;" ::: "memory")
#define TC_WAIT_LD()     asm volatile("tcgen05.wait::ld.sync.aligned;" ::: "memory")
#define FENCE_ASYNC()    asm volatile("fence.proxy.async.shared::cta;" ::: "memory")
__device__ __forceinline__ void tc_mma(uint32_t d, uint64_t ad, uint64_t bd, uint32_t idesc, uint32_t en) {
    asm volatile("{\n\t.reg .pred p;\n\tsetp.ne.u32 p, %5, 0;\n\t"
                 "tcgen05.mma.cta_group::1.kind::f16 [%0], %1, %2, %3, {%4,%4,%4,%4}, p;\n\t}"
                 :: "r"(d), "l"(ad), "l"(bd), "r"(idesc), "r"(0u), "r"(en) : "memory");
}
#define TC_LD_X32(r, tm) \
    asm volatile("tcgen05.ld.sync.aligned.32x32b.x32.b32 " \
        "{%0,%1,%2,%3,%4,%5,%6,%7,%8,%9,%10,%11,%12,%13,%14,%15," \
        "%16,%17,%18,%19,%20,%21,%22,%23,%24,%25,%26,%27,%28,%29,%30,%31}, [%32];" \
        : "=r"((r)[0]),"=r"((r)[1]),"=r"((r)[2]),"=r"((r)[3]),"=r"((r)[4]),"=r"((r)[5]),"=r"((r)[6]),"=r"((r)[7]), \
          "=r"((r)[8]),"=r"((r)[9]),"=r"((r)[10]),"=r"((r)[11]),"=r"((r)[12]),"=r"((r)[13]),"=r"((r)[14]),"=r"((r)[15]), \
          "=r"((r)[16]),"=r"((r)[17]),"=r"((r)[18]),"=r"((r)[19]),"=r"((r)[20]),"=r"((r)[21]),"=r"((r)[22]),"=r"((r)[23]), \
          "=r"((r)[24]),"=r"((r)[25]),"=r"((r)[26]),"=r"((r)[27]),"=r"((r)[28]),"=r"((r)[29]),"=r"((r)[30]),"=r"((r)[31]) \
        : "r"(tm))
constexpr uint32_t IDESC128 = 0x8200490u;   // M=128, N=128 (verified family)
constexpr uint32_t IDESC64  = 0x8100490u;   // M=128, N=64
#endif  // TC_OK

// ---------------------------------------------------------------------------
// Unified tcgen05 GEMM, double-buffered.
// EPI 0 attn : A = x fp32 (K=1024), N tiles over 2048; store fp32 q|v (+attn_b)
// EPI 1 freq : A = shifted z fp32, scaled inline (K=2048, N=64); sincos -> sc hi/lo
// EPI 2 out  : A = sc hi/lo presplit (K=128, N=128); store z fp32 (+out_b) + atomicMax
// EPI 3 proj : A = z*scale*v fp32 (K=1024, N=128); store out fp32 (+proj_b)
// ---------------------------------------------------------------------------
template<int EPI>
__global__ void __launch_bounds__(256) __cluster_dims__(1, 1, 1)
tc_gemm(const void* __restrict__ A0, const void* __restrict__ A1,
        const float* __restrict__ scale, const float* __restrict__ identity,
        const __nv_bfloat16* __restrict__ Bhi, const __nv_bfloat16* __restrict__ Blo,
        const float* __restrict__ bias,
        float* __restrict__ O0, float* __restrict__ O1,
        __nv_bfloat16* __restrict__ OH, __nv_bfloat16* __restrict__ OL,
        float* __restrict__ gmaxO, int Kdim, int nshift)
{
#if TC_OK
    extern __shared__ char sm[];
    const uint32_t sb = smem_u32(sm);
    const int tid = threadIdx.x, wid = tid >> 5, lane = tid & 31;
    const int bm = blockIdx.y * 128, bn = blockIdx.x * ((EPI == 1) ? 64 : 128);
    const int NT = (EPI == 1) ? 64 : 128;
    const uint32_t idesc = (EPI == 1) ? IDESC64 : IDESC128;
    const int KT = Kdim >> 6;

    if (wid == 0) TC_ALLOC(sb + 0, 128);
    if (tid == 0) { MBAR_INIT(sb + 8, 1); MBAR_INIT(sb + 16, 1); }
    __syncthreads();
    uint32_t tmem;
    asm volatile("ld.shared.b32 %0, [%1];" : "=r"(tmem) : "r"(sb + 0));

    const int arow = tid >> 1, ah = tid & 1;
    // per-row constants for fp32 paths
    float sOwn = 1.f;
    if (EPI == 3) sOwn = 1.f / (scale[bm + arow] + EPS);
    float sCur = 1.f, sPrev = 1.f;
    const float* zPrevRow = nullptr;
    if (EPI == 1) {
        int r = bm + arow, t = r & (Tv - 1);
        if (scale) sCur = 1.f / (scale[r] + EPS);
        if (t >= nshift) {
            zPrevRow = (const float*)A0 + (size_t)(r - nshift) * Cv;
            if (scale) sPrev = 1.f / (scale[r - nshift] + EPS);
        }
    }

    int ph[2] = {0, 0};
#pragma unroll 1
    for (int kt = 0; kt < KT; kt++) {
        const int b = kt & 1;
        if (kt >= 2) { mbar_wait(sb + 8 + 8 * b, ph[b]); ph[b] ^= 1; }
        char* tb = sm + 1024 + b * 65536;
        const int k0 = kt * 64;
        // ---- A tile: hi at +0, lo at +16384 ----
        if (EPI == 2) {
            const __nv_bfloat16* sh = (const __nv_bfloat16*)A0 + (size_t)(bm + arow) * 128 + k0 + 32 * ah;
            const __nv_bfloat16* sl = (const __nv_bfloat16*)A1 + (size_t)(bm + arow) * 128 + k0 + 32 * ah;
#pragma unroll
            for (int j = 0; j < 4; j++) {
                int off = arow * 128 + (32 * ah + 8 * j) * 2;
                *reinterpret_cast<uint4*>(tb + SWZ(off))         = reinterpret_cast<const uint4*>(sh)[j];
                *reinterpret_cast<uint4*>(tb + 16384 + SWZ(off)) = reinterpret_cast<const uint4*>(sl)[j];
            }
        } else {
            const float* src; const float* vsrc = nullptr; float s;
            if (EPI == 1) {
                if (k0 < 1024) {
                    int kg = k0 + 32 * ah;
                    if (zPrevRow) { src = zPrevRow + kg; s = sPrev; }
                    else          { src = identity + kg; s = 1.f; }
                } else {
                    src = (const float*)A0 + (size_t)(bm + arow) * Cv + (k0 - 1024) + 32 * ah;
                    s = sCur;
                }
            } else {
                src = (const float*)A0 + (size_t)(bm + arow) * Kdim + k0 + 32 * ah;
                s = (EPI == 3) ? sOwn : 1.f;
                if (EPI == 3) vsrc = (const float*)A1 + (size_t)(bm + arow) * Kdim + k0 + 32 * ah;
            }
#pragma unroll
            for (int j = 0; j < 4; j++) {
                float4 a0 = reinterpret_cast<const float4*>(src)[2 * j];
                float4 a1 = reinterpret_cast<const float4*>(src)[2 * j + 1];
                if (EPI == 3) {
                    float4 v0 = reinterpret_cast<const float4*>(vsrc)[2 * j];
                    float4 v1 = reinterpret_cast<const float4*>(vsrc)[2 * j + 1];
                    a0.x *= v0.x; a0.y *= v0.y; a0.z *= v0.z; a0.w *= v0.w;
                    a1.x *= v1.x; a1.y *= v1.y; a1.z *= v1.z; a1.w *= v1.w;
                }
                float f[8] = {a0.x * s, a0.y * s, a0.z * s, a0.w * s,
                              a1.x * s, a1.y * s, a1.z * s, a1.w * s};
                __nv_bfloat16 h[8], l[8];
#pragma unroll
                for (int e = 0; e < 8; e++) split1(f[e], h[e], l[e]);
                uint4 H = {packbf(h[0], h[1]), packbf(h[2], h[3]), packbf(h[4], h[5]), packbf(h[6], h[7])};
                uint4 L = {packbf(l[0], l[1]), packbf(l[2], l[3]), packbf(l[4], l[5]), packbf(l[6], l[7])};
                int off = arow * 128 + (32 * ah + 8 * j) * 2;
                *reinterpret_cast<uint4*>(tb + SWZ(off))         = H;
                *reinterpret_cast<uint4*>(tb + 16384 + SWZ(off)) = L;
            }
        }
        // ---- B tile: hi at +32768, lo at +49152 ----
        for (int it = tid; it < NT * 2; it += 256) {
            int row = it >> 1, h = it & 1;
            const __nv_bfloat16* bh = Bhi + (size_t)(bn + row) * Kdim + k0 + 32 * h;
            const __nv_bfloat16* bl = Blo + (size_t)(bn + row) * Kdim + k0 + 32 * h;
#pragma unroll
            for (int j = 0; j < 4; j++) {
                int off = row * 128 + (32 * h + 8 * j) * 2;
                *reinterpret_cast<uint4*>(tb + 32768 + SWZ(off)) = reinterpret_cast<const uint4*>(bh)[j];
                *reinterpret_cast<uint4*>(tb + 49152 + SWZ(off)) = reinterpret_cast<const uint4*>(bl)[j];
            }
        }
        FENCE_ASYNC();
        __syncthreads();
        if (wid == 0 && elect1()) {
            uint32_t base = sb + 1024 + b * 65536;
            uint64_t dAh = mkdesc(base), dAl = mkdesc(base + 16384);
            uint64_t dBh = mkdesc(base + 32768), dBl = mkdesc(base + 49152);
#pragma unroll
            for (int s2 = 0; s2 < 4; s2++) {
                tc_mma(tmem, dAh + 2 * s2, dBh + 2 * s2, idesc, (kt == 0 && s2 == 0) ? 0u : 1u);
                tc_mma(tmem, dAh + 2 * s2, dBl + 2 * s2, idesc, 1u);
                tc_mma(tmem, dAl + 2 * s2, dBh + 2 * s2, idesc, 1u);
            }
            TC_COMMIT(sb + 8 + 8 * b);
        }
    }
    { const int bl = (KT - 1) & 1; mbar_wait(sb + 8 + 8 * bl, ph[bl]); }
    TC_FENCE_AFTER();

    if (wid < 4) {
        const int r = bm + wid * 32 + lane;
        if (EPI == 1) {
            float f[64];
#pragma unroll
            for (int c4 = 0; c4 < 2; c4++) {
                uint32_t regs[32];
                TC_LD_X32(regs, tmem + 32 * c4);
                TC_WAIT_LD();
#pragma unroll
                for (int e = 0; e < 32; e++) f[32 * c4 + e] = __uint_as_float(regs[e]);
            }
#pragma unroll
            for (int e = 0; e < 32; e++) {
                float s0, c0, s1, c1;
                sincosf(f[2 * e]     + bias[2 * e],     &s0, &c0);
                sincosf(f[2 * e + 1] + bias[2 * e + 1], &s1, &c1);
                __nv_bfloat16 h0, l0, h1, l1, h2, l2, h3, l3;
                split1(s0, h0, l0); split1(s1, h1, l1);
                split1(c0, h2, l2); split1(c1, h3, l3);
                size_t os = (size_t)r * 64 + e, oc = os + 32;
                reinterpret_cast<__nv_bfloat162*>(OH)[os] = __nv_bfloat162{h0, h1};
                reinterpret_cast<__nv_bfloat162*>(OL)[os] = __nv_bfloat162{l0, l1};
                reinterpret_cast<__nv_bfloat162*>(OH)[oc] = __nv_bfloat162{h2, h3};
                reinterpret_cast<__nv_bfloat162*>(OL)[oc] = __nv_bfloat162{l2, l3};
            }
        } else {
            float rowmax = 0.f;
#pragma unroll 1
            for (int c4 = 0; c4 < 4; c4++) {
                uint32_t regs[32];
                TC_LD_X32(regs, tmem + 32 * c4);
                TC_WAIT_LD();
                const int col0 = bn + 32 * c4;
                float* dst; int cc;
                if (EPI == 0) { dst = (col0 < 1024) ? O0 : O1; cc = (col0 < 1024) ? col0 : col0 - 1024; }
                else          { dst = O0; cc = col0; }
#pragma unroll
                for (int e = 0; e < 8; e++) {
                    float4 o;
                    o.x = __uint_as_float(regs[4 * e + 0]) + bias[col0 + 4 * e + 0];
                    o.y = __uint_as_float(regs[4 * e + 1]) + bias[col0 + 4 * e + 1];
                    o.z = __uint_as_float(regs[4 * e + 2]) + bias[col0 + 4 * e + 2];
                    o.w = __uint_as_float(regs[4 * e + 3]) + bias[col0 + 4 * e + 3];
                    if (EPI == 2)
                        rowmax = fmaxf(rowmax,
                                 fmaxf(fmaxf(fabsf(o.x), fabsf(o.y)), fmaxf(fabsf(o.z), fabsf(o.w))));
                    *reinterpret_cast<float4*>(dst + (size_t)r * 1024 + cc + 4 * e) = o;
                }
            }
            if (EPI == 2)
                atomicMax(reinterpret_cast<unsigned int*>(gmaxO + r), __float_as_uint(rowmax));
        }
    }
    __syncthreads();
    if (tid == 0) { MBAR_INVAL(sb + 8); MBAR_INVAL(sb + 16); }
    __syncthreads();
    if (wid == 0) { TC_RELINQ(); TC_DEALLOC(tmem, 128); }
#endif  // TC_OK
}

// ============================ host ============================
extern "C" void kernel_launch(void* const* d_in, const int* in_sizes, int n_in,
                              void* d_out, int out_size)
{
    const float* x        = (const float*)d_in[0];
    const float* attn_W   = (const float*)d_in[1];
    const float* attn_b   = (const float*)d_in[2];
    const float* freq_W   = (const float*)d_in[3];
    const float* freq_b   = (const float*)d_in[4];
    const float* out_W    = (const float*)d_in[5];
    const float* out_b    = (const float*)d_in[6];
    const float* proj_W   = (const float*)d_in[7];
    const float* proj_b   = (const float*)d_in[8];
    const float* identity = (const float*)d_in[9];
    float* out = (float*)d_out;

    cudaFuncSetAttribute(tc_gemm<0>, cudaFuncAttributeMaxDynamicSharedMemorySize, SMEMSZ);
    cudaFuncSetAttribute(tc_gemm<1>, cudaFuncAttributeMaxDynamicSharedMemorySize, SMEMSZ);
    cudaFuncSetAttribute(tc_gemm<2>, cudaFuncAttributeMaxDynamicSharedMemorySize, SMEMSZ);
    cudaFuncSetAttribute(tc_gemm<3>, cudaFuncAttributeMaxDynamicSharedMemorySize, SMEMSZ);

    float *z0, *z1, *v, *gmax;
    __nv_bfloat16 *schi, *sclo, *aWhi, *aWlo, *fWhi, *fWlo, *oWhi, *oWlo, *pWhi, *pWlo;
    cudaGetSymbolAddress((void**)&z0, g_z0);
    cudaGetSymbolAddress((void**)&z1, g_z1);
    cudaGetSymbolAddress((void**)&v,  g_v);
    cudaGetSymbolAddress((void**)&gmax, g_gmax);
    cudaGetSymbolAddress((void**)&schi, g_schi); cudaGetSymbolAddress((void**)&sclo, g_sclo);
    cudaGetSymbolAddress((void**)&aWhi, g_aWhi); cudaGetSymbolAddress((void**)&aWlo, g_aWlo);
    cudaGetSymbolAddress((void**)&fWhi, g_fWhi); cudaGetSymbolAddress((void**)&fWlo, g_fWlo);
    cudaGetSymbolAddress((void**)&oWhi, g_oWhi); cudaGetSymbolAddress((void**)&oWlo, g_oWlo);
    cudaGetSymbolAddress((void**)&pWhi, g_pWhi); cudaGetSymbolAddress((void**)&pWlo, g_pWlo);

    // prep
    zero_gmax_kernel<<<(11 * Md + 1023) / 1024, 1024>>>();
    tsplit_kernel<<<(1024 * 2048 + 255) / 256, 256>>>(attn_W, aWhi, aWlo, 1024, 2048);
    tsplit_kernel<<<(2048 * 64 + 255) / 256, 256>>>(freq_W, fWhi, fWlo, 2048, 64);
    tsplit_kernel<<<(128 * 1024 + 255) / 256, 256>>>(out_W, oWhi, oWlo, 128, 1024);
    tsplit_kernel<<<(1024 * 1024 + 255) / 256, 256>>>(proj_W, pWhi, pWlo, 1024, 1024);

    // attn: [q|v] = x @ attn_W + attn_b  (q fp32 -> z0, v fp32)
    tc_gemm<0><<<dim3(16, 128), 256, SMEMSZ>>>(x, nullptr, nullptr, nullptr,
                                               aWhi, aWlo, attn_b,
                                               z0, v, nullptr, nullptr, nullptr, 1024, 0);

    // scan: 11 iterations; z unnormalized, scale applied at consumer via gmax
    float* zcur = z0;
    float* znxt = z1;
    for (int it = 0, n = 1; n < Tv; n <<= 1, it++) {
        const float* sc_prev = (it == 0) ? nullptr : gmax + (size_t)(it - 1) * Md;
        tc_gemm<1><<<dim3(1, 128), 256, SMEMSZ>>>(zcur, nullptr, sc_prev, identity,
                                                  fWhi, fWlo, freq_b,
                                                  nullptr, nullptr, schi, sclo, nullptr, 2048, n);
        tc_gemm<2><<<dim3(8, 128), 256, SMEMSZ>>>(schi, sclo, nullptr, nullptr,
                                                  oWhi, oWlo, out_b,
                                                  znxt, nullptr, nullptr, nullptr,
                                                  gmax + (size_t)it * Md, 128, 0);
        float* t = zcur; zcur = znxt; znxt = t;
    }

    // proj: out = (z*scale*v) @ proj_W + proj_b
    tc_gemm<3><<<dim3(8, 128), 256, SMEMSZ>>>(zcur, v, gmax + (size_t)10 * Md, nullptr,
                                              pWhi, pWlo, proj_b,
                                              out, nullptr, nullptr, nullptr, nullptr, 1024, 0);
}

// round 13
// speedup vs baseline: 2.4847x; 1.1748x over previous
#include <cuda_runtime.h>
#include <cuda_bf16.h>
#include <math.h>
#include <stdint.h>

constexpr int Tv = 2048, Cv = 1024, Md = 16384;
constexpr float EPS = 1e-6f;
constexpr int SMEMSZ = 1024 + 2 * 65536;   // header + 2 bufs x 4 tiles x 16KB

#if defined(__CUDA_ARCH_FEAT_SM103_ALL) || defined(__CUDA_ARCH_SPECIFIC__) || defined(__CUDA_ARCH_FAMILY_SPECIFIC__)
#define TC_OK 1
#else
#define TC_OK 0
#endif

// ---------------- device-global scratch ----------------
__device__ __nv_bfloat16 g_zhi0[(size_t)Md * Cv], g_zlo0[(size_t)Md * Cv];
__device__ __nv_bfloat16 g_zhi1[(size_t)Md * Cv], g_zlo1[(size_t)Md * Cv];
__device__ __nv_bfloat16 g_xhi[(size_t)Md * Cv],  g_xlo[(size_t)Md * Cv];
__device__ float g_v[(size_t)Md * Cv];
__device__ float g_G[(size_t)Md * 128];
__device__ float g_gmax[11 * Md];
__device__ float g_idW1[64];
__device__ __nv_bfloat16 g_schi[(size_t)Md * 128], g_sclo[(size_t)Md * 128];
__device__ __nv_bfloat16 g_aWhi[(size_t)2048 * 1024], g_aWlo[(size_t)2048 * 1024];
__device__ __nv_bfloat16 g_cWhi[(size_t)128 * 1024],  g_cWlo[(size_t)128 * 1024];   // [W1|W2] cat, [N=128][K=1024]
__device__ __nv_bfloat16 g_oWhi[(size_t)1024 * 128],  g_oWlo[(size_t)1024 * 128];
__device__ __nv_bfloat16 g_pWhi[(size_t)1024 * 1024], g_pWlo[(size_t)1024 * 1024];

// ---------------- helpers ----------------
__device__ __forceinline__ void split1(float x, __nv_bfloat16& h, __nv_bfloat16& l) {
    h = __float2bfloat16_rn(x);
    l = __float2bfloat16_rn(x - __bfloat162float(h));
}

// ---------------- prep kernels ----------------
__global__ void tsplit_kernel(const float* __restrict__ W, __nv_bfloat16* __restrict__ hi,
                              __nv_bfloat16* __restrict__ lo, int K, int N) {
    size_t i = (size_t)blockIdx.x * 256 + threadIdx.x;
    if (i >= (size_t)K * N) return;
    int n = (int)(i / K), k = (int)(i % K);
    split1(W[(size_t)k * N + n], hi[i], lo[i]);
}
// Wcat: rows 0..63 = W1^T (freq_W[k][n]), rows 64..127 = W2^T (freq_W[1024+k][n-64])
__global__ void tsplit_wcat_kernel(const float* __restrict__ freq_W) {
    size_t i = (size_t)blockIdx.x * 256 + threadIdx.x;
    if (i >= (size_t)128 * 1024) return;
    int n = (int)(i / 1024), k = (int)(i % 1024);
    float w = (n < 64) ? freq_W[(size_t)k * 64 + n] : freq_W[(size_t)(1024 + k) * 64 + (n - 64)];
    split1(w, g_cWhi[i], g_cWlo[i]);
}
__global__ void splitx_kernel(const float* __restrict__ X, __nv_bfloat16* __restrict__ hi,
                              __nv_bfloat16* __restrict__ lo, size_t n4) {
    size_t i = (size_t)blockIdx.x * 256 + threadIdx.x;
    if (i >= n4) return;
    float4 x = reinterpret_cast<const float4*>(X)[i];
    __nv_bfloat16 h[4], l[4];
    split1(x.x, h[0], l[0]); split1(x.y, h[1], l[1]);
    split1(x.z, h[2], l[2]); split1(x.w, h[3], l[3]);
    reinterpret_cast<__nv_bfloat162*>(hi)[2 * i]     = __nv_bfloat162{h[0], h[1]};
    reinterpret_cast<__nv_bfloat162*>(hi)[2 * i + 1] = __nv_bfloat162{h[2], h[3]};
    reinterpret_cast<__nv_bfloat162*>(lo)[2 * i]     = __nv_bfloat162{l[0], l[1]};
    reinterpret_cast<__nv_bfloat162*>(lo)[2 * i + 1] = __nv_bfloat162{l[2], l[3]};
}
__global__ void zero_gmax_kernel() {
    int i = blockIdx.x * 1024 + threadIdx.x;
    if (i < 11 * Md) g_gmax[i] = 0.f;
}
// idW1[n] = sum_k identity[k] * freq_W[k][n], n<64. 256 thr: 64 n x 4 k-chunks.
__global__ void idw1_kernel(const float* __restrict__ identity, const float* __restrict__ freq_W) {
    int tid = threadIdx.x, nn = tid & 63, part = tid >> 6;
    float acc = 0.f;
    for (int k = part * 256; k < part * 256 + 256; k++)
        acc += identity[k] * freq_W[(size_t)k * 64 + nn];
    __shared__ float red[256];
    red[tid] = acc;
    __syncthreads();
    if (tid < 64) g_idW1[tid] = red[tid] + red[tid + 64] + red[tid + 128] + red[tid + 192];
}
// fuse: f = s_prev*G1[r-n] + s_cur*G2[r] + freq_b; sc = split(sincos(f)). 8 rows/block.
__global__ void __launch_bounds__(256)
fuse_kernel(const float* __restrict__ G, const float* __restrict__ gmax_prev,
            const float* __restrict__ freq_b,
            __nv_bfloat16* __restrict__ SH, __nv_bfloat16* __restrict__ SL, int n) {
    int tid = threadIdx.x;
    int r = blockIdx.x * 8 + (tid >> 5), lane = tid & 31;
    int t = r & (Tv - 1);
    float scur = gmax_prev ? 1.f / (gmax_prev[r] + EPS) : 1.f;
    float2 g2 = *reinterpret_cast<const float2*>(G + (size_t)r * 128 + 64 + 2 * lane);
    float2 g1; float sp;
    if (t >= n) {
        g1 = *reinterpret_cast<const float2*>(G + (size_t)(r - n) * 128 + 2 * lane);
        sp = gmax_prev ? 1.f / (gmax_prev[r - n] + EPS) : 1.f;
    } else {
        g1 = *reinterpret_cast<const float2*>(g_idW1 + 2 * lane);
        sp = 1.f;
    }
    float2 fb = *reinterpret_cast<const float2*>(freq_b + 2 * lane);
    float f0 = sp * g1.x + scur * g2.x + fb.x;
    float f1 = sp * g1.y + scur * g2.y + fb.y;
    float s0, c0, s1, c1;
    sincosf(f0, &s0, &c0);
    sincosf(f1, &s1, &c1);
    __nv_bfloat16 hs0, ls0, hs1, ls1, hc0, lc0, hc1, lc1;
    split1(s0, hs0, ls0); split1(s1, hs1, ls1);
    split1(c0, hc0, lc0); split1(c1, hc1, lc1);
    size_t base = (size_t)r * 64 + lane;           // bf162 units; cos at +32
    reinterpret_cast<__nv_bfloat162*>(SH)[base]      = __nv_bfloat162{hs0, hs1};
    reinterpret_cast<__nv_bfloat162*>(SL)[base]      = __nv_bfloat162{ls0, ls1};
    reinterpret_cast<__nv_bfloat162*>(SH)[base + 32] = __nv_bfloat162{hc0, hc1};
    reinterpret_cast<__nv_bfloat162*>(SL)[base + 32] = __nv_bfloat162{lc0, lc1};
}
// y = (zhi+zlo) * s * v, split -> yhi/ylo. grid=Md, 256 thr (4 cols each).
__global__ void __launch_bounds__(256)
mulv_split_kernel(const __nv_bfloat16* __restrict__ ZH, const __nv_bfloat16* __restrict__ ZL,
                  const float* __restrict__ v, const float* __restrict__ gmax,
                  __nv_bfloat16* __restrict__ YH, __nv_bfloat16* __restrict__ YL) {
    int r = blockIdx.x, tid = threadIdx.x;
    float s = 1.f / (gmax[r] + EPS);
    __nv_bfloat162 h0 = reinterpret_cast<const __nv_bfloat162*>(ZH)[(size_t)r * 512 + 2 * tid];
    __nv_bfloat162 h1 = reinterpret_cast<const __nv_bfloat162*>(ZH)[(size_t)r * 512 + 2 * tid + 1];
    __nv_bfloat162 l0 = reinterpret_cast<const __nv_bfloat162*>(ZL)[(size_t)r * 512 + 2 * tid];
    __nv_bfloat162 l1 = reinterpret_cast<const __nv_bfloat162*>(ZL)[(size_t)r * 512 + 2 * tid + 1];
    float4 v4 = reinterpret_cast<const float4*>(v + (size_t)r * Cv)[tid];
    float y0 = (__bfloat162float(h0.x) + __bfloat162float(l0.x)) * s * v4.x;
    float y1 = (__bfloat162float(h0.y) + __bfloat162float(l0.y)) * s * v4.y;
    float y2 = (__bfloat162float(h1.x) + __bfloat162float(l1.x)) * s * v4.z;
    float y3 = (__bfloat162float(h1.y) + __bfloat162float(l1.y)) * s * v4.w;
    __nv_bfloat16 h[4], l[4];
    split1(y0, h[0], l[0]); split1(y1, h[1], l[1]);
    split1(y2, h[2], l[2]); split1(y3, h[3], l[3]);
    reinterpret_cast<__nv_bfloat162*>(YH)[(size_t)r * 512 + 2 * tid]     = __nv_bfloat162{h[0], h[1]};
    reinterpret_cast<__nv_bfloat162*>(YH)[(size_t)r * 512 + 2 * tid + 1] = __nv_bfloat162{h[2], h[3]};
    reinterpret_cast<__nv_bfloat162*>(YL)[(size_t)r * 512 + 2 * tid]     = __nv_bfloat162{l[0], l[1]};
    reinterpret_cast<__nv_bfloat162*>(YL)[(size_t)r * 512 + 2 * tid + 1] = __nv_bfloat162{l[2], l[3]};
}

#if TC_OK
__device__ __forceinline__ uint32_t smem_u32(const void* p) {
    uint32_t a;
    asm("{ .reg .u64 t; cvta.to.shared.u64 t, %1; cvt.u32.u64 %0, t; }" : "=r"(a) : "l"(p));
    return a;
}
__device__ __forceinline__ bool elect1() {
    uint32_t p;
    asm volatile("{\n\t.reg .pred p;\n\telect.sync _|p, 0xFFFFFFFF;\n\tselp.b32 %0,1,0,p;\n\t}" : "=r"(p));
    return p != 0;
}
#define SWZ(o) ((o) ^ (((o) >> 3) & 0x70))
__device__ __forceinline__ uint64_t mkdesc(uint32_t a) {
    const uint64_t base = (uint64_t(2) << 61) | (uint64_t(1) << 46) | (uint64_t(64) << 32) | (uint64_t(1) << 16);
    return base | ((uint64_t)(a >> 4) & 0x3FFF);
}
#define MBAR_INIT(mb, c) asm volatile("mbarrier.init.shared.b64 [%0], %1;" :: "r"(mb), "r"((uint32_t)(c)) : "memory")
#define MBAR_INVAL(mb)   asm volatile("mbarrier.inval.shared.b64 [%0];" :: "r"(mb) : "memory")
__device__ __forceinline__ void mbar_wait(uint32_t mb, uint32_t ph) {
    uint32_t done;
    asm volatile("{\n\t.reg .pred p;\n\tmbarrier.try_wait.parity.acquire.cta.shared::cta.b64 p, [%1], %2;\n\tselp.b32 %0,1,0,p;\n\t}"
                 : "=r"(done) : "r"(mb), "r"(ph) : "memory");
    if (!done)
        asm volatile("{\n\t.reg .pred P1;\nWL_%=:\n\tmbarrier.try_wait.parity.acquire.cta.shared::cta.b64 P1, [%0], %1, 0x989680;\n\t@P1 bra.uni WD_%=;\n\tbra.uni WL_%=;\nWD_%=:\n\t}"
                     :: "r"(mb), "r"(ph) : "memory");
}
#define TC_ALLOC(sm, n)  asm volatile("tcgen05.alloc.cta_group::1.sync.aligned.shared::cta.b32 [%0], %1;" :: "r"(sm), "r"((uint32_t)(n)) : "memory")
#define TC_DEALLOC(t, n) asm volatile("tcgen05.dealloc.cta_group::1.sync.aligned.b32 %0, %1;" :: "r"(t), "r"((uint32_t)(n)))
#define TC_RELINQ()      asm volatile("tcgen05.relinquish_alloc_permit.cta_group::1.sync.aligned;")
#define TC_COMMIT(mb)    asm volatile("tcgen05.commit.cta_group::1.mbarrier::arrive::one.shared::cluster.b64 [%0];" :: "r"(mb) : "memory")
#define TC_FENCE_AFTER() asm volatile("tcgen05.fence::after_thread_sync;" ::: "memory")
#define TC_WAIT_LD()     asm volatile("tcgen05.wait::ld.sync.aligned;" ::: "memory")
#define FENCE_ASYNC()    asm volatile("fence.proxy.async.shared::cta;" ::: "memory")
__device__ __forceinline__ void tc_mma(uint32_t d, uint64_t ad, uint64_t bd, uint32_t idesc, uint32_t en) {
    asm volatile("{\n\t.reg .pred p;\n\tsetp.ne.u32 p, %5, 0;\n\t"
                 "tcgen05.mma.cta_group::1.kind::f16 [%0], %1, %2, %3, {%4,%4,%4,%4}, p;\n\t}"
                 :: "r"(d), "l"(ad), "l"(bd), "r"(idesc), "r"(0u), "r"(en) : "memory");
}
#define TC_LD_X32(r, tm) \
    asm volatile("tcgen05.ld.sync.aligned.32x32b.x32.b32 " \
        "{%0,%1,%2,%3,%4,%5,%6,%7,%8,%9,%10,%11,%12,%13,%14,%15," \
        "%16,%17,%18,%19,%20,%21,%22,%23,%24,%25,%26,%27,%28,%29,%30,%31}, [%32];" \
        : "=r"((r)[0]),"=r"((r)[1]),"=r"((r)[2]),"=r"((r)[3]),"=r"((r)[4]),"=r"((r)[5]),"=r"((r)[6]),"=r"((r)[7]), \
          "=r"((r)[8]),"=r"((r)[9]),"=r"((r)[10]),"=r"((r)[11]),"=r"((r)[12]),"=r"((r)[13]),"=r"((r)[14]),"=r"((r)[15]), \
          "=r"((r)[16]),"=r"((r)[17]),"=r"((r)[18]),"=r"((r)[19]),"=r"((r)[20]),"=r"((r)[21]),"=r"((r)[22]),"=r"((r)[23]), \
          "=r"((r)[24]),"=r"((r)[25]),"=r"((r)[26]),"=r"((r)[27]),"=r"((r)[28]),"=r"((r)[29]),"=r"((r)[30]),"=r"((r)[31]) \
        : "r"(tm))
constexpr uint32_t IDESC128 = 0x8200490u;   // M=128, N=128 (verified family)
#endif  // TC_OK

// ---------------------------------------------------------------------------
// Unified tcgen05 GEMM (all A-operands presplit bf16 hi/lo; pure-copy loads).
// EPI 0 attn : K=1024, N-blocks over 2048; q cols -> split store OH/OL, v -> fp32 O0
// EPI 1 G    : K=1024, N=128; fp32 store (no bias)
// EPI 2 out  : K=128,  N=128 x8; +bias, rowmax->atomicMax(gmaxO), split -> OH/OL
// EPI 3 proj : K=1024, N=128 x8; +bias -> fp32 O0
// ---------------------------------------------------------------------------
template<int EPI>
__global__ void __launch_bounds__(256) __cluster_dims__(1, 1, 1)
tc_gemm(const __nv_bfloat16* __restrict__ Ahi, const __nv_bfloat16* __restrict__ Alo,
        const __nv_bfloat16* __restrict__ Bhi, const __nv_bfloat16* __restrict__ Blo,
        const float* __restrict__ bias,
        float* __restrict__ O0,
        __nv_bfloat16* __restrict__ OH, __nv_bfloat16* __restrict__ OL,
        float* __restrict__ gmaxO, int Kdim)
{
#if TC_OK
    extern __shared__ char sm[];
    const uint32_t sb = smem_u32(sm);
    const int tid = threadIdx.x, wid = tid >> 5, lane = tid & 31;
    const int bm = blockIdx.y * 128, bn = blockIdx.x * 128;
    const int KT = Kdim >> 6;

    if (wid == 0) TC_ALLOC(sb + 0, 128);
    if (tid == 0) { MBAR_INIT(sb + 8, 1); MBAR_INIT(sb + 16, 1); }
    __syncthreads();
    uint32_t tmem;
    asm volatile("ld.shared.b32 %0, [%1];" : "=r"(tmem) : "r"(sb + 0));

    const int arow = tid >> 1, ah = tid & 1;
    int ph[2] = {0, 0};
#pragma unroll 1
    for (int kt = 0; kt < KT; kt++) {
        const int b = kt & 1;
        if (kt >= 2) { mbar_wait(sb + 8 + 8 * b, ph[b]); ph[b] ^= 1; }
        char* tb = sm + 1024 + b * 65536;
        const int k0 = kt * 64;
        // A tile: pure copy (hi at +0, lo at +16384)
        {
            const __nv_bfloat16* sh = Ahi + (size_t)(bm + arow) * Kdim + k0 + 32 * ah;
            const __nv_bfloat16* sl = Alo + (size_t)(bm + arow) * Kdim + k0 + 32 * ah;
#pragma unroll
            for (int j = 0; j < 4; j++) {
                int off = arow * 128 + (32 * ah + 8 * j) * 2;
                *reinterpret_cast<uint4*>(tb + SWZ(off))         = reinterpret_cast<const uint4*>(sh)[j];
                *reinterpret_cast<uint4*>(tb + 16384 + SWZ(off)) = reinterpret_cast<const uint4*>(sl)[j];
            }
        }
        // B tile: pure copy (hi at +32768, lo at +49152)
        {
            const __nv_bfloat16* bh = Bhi + (size_t)(bn + arow) * Kdim + k0 + 32 * ah;
            const __nv_bfloat16* bl = Blo + (size_t)(bn + arow) * Kdim + k0 + 32 * ah;
#pragma unroll
            for (int j = 0; j < 4; j++) {
                int off = arow * 128 + (32 * ah + 8 * j) * 2;
                *reinterpret_cast<uint4*>(tb + 32768 + SWZ(off)) = reinterpret_cast<const uint4*>(bh)[j];
                *reinterpret_cast<uint4*>(tb + 49152 + SWZ(off)) = reinterpret_cast<const uint4*>(bl)[j];
            }
        }
        FENCE_ASYNC();
        __syncthreads();
        if (wid == 0 && elect1()) {
            uint32_t base = sb + 1024 + b * 65536;
            uint64_t dAh = mkdesc(base), dAl = mkdesc(base + 16384);
            uint64_t dBh = mkdesc(base + 32768), dBl = mkdesc(base + 49152);
#pragma unroll
            for (int s2 = 0; s2 < 4; s2++) {
                tc_mma(tmem, dAh + 2 * s2, dBh + 2 * s2, IDESC128, (kt == 0 && s2 == 0) ? 0u : 1u);
                tc_mma(tmem, dAh + 2 * s2, dBl + 2 * s2, IDESC128, 1u);
                tc_mma(tmem, dAl + 2 * s2, dBh + 2 * s2, IDESC128, 1u);
            }
            TC_COMMIT(sb + 8 + 8 * b);
        }
    }
    { const int bl = (KT - 1) & 1; mbar_wait(sb + 8 + 8 * bl, ph[bl]); }
    TC_FENCE_AFTER();

    if (wid < 4) {
        const int r = bm + wid * 32 + lane;
        float rowmax = 0.f;
#pragma unroll 1
        for (int c4 = 0; c4 < 4; c4++) {
            uint32_t regs[32];
            TC_LD_X32(regs, tmem + 32 * c4);
            TC_WAIT_LD();
            const int col0 = bn + 32 * c4;
            const bool q_split = (EPI == 0 && col0 < 1024) || (EPI == 2);
#pragma unroll
            for (int e = 0; e < 8; e++) {
                float4 o;
                o.x = __uint_as_float(regs[4 * e + 0]);
                o.y = __uint_as_float(regs[4 * e + 1]);
                o.z = __uint_as_float(regs[4 * e + 2]);
                o.w = __uint_as_float(regs[4 * e + 3]);
                if (EPI != 1) {
                    o.x += bias[col0 + 4 * e + 0]; o.y += bias[col0 + 4 * e + 1];
                    o.z += bias[col0 + 4 * e + 2]; o.w += bias[col0 + 4 * e + 3];
                }
                if (EPI == 2)
                    rowmax = fmaxf(rowmax,
                             fmaxf(fmaxf(fabsf(o.x), fabsf(o.y)), fmaxf(fabsf(o.z), fabsf(o.w))));
                if (q_split) {
                    __nv_bfloat16 h0, l0, h1, l1, h2, l2, h3, l3;
                    split1(o.x, h0, l0); split1(o.y, h1, l1);
                    split1(o.z, h2, l2); split1(o.w, h3, l3);
                    size_t o2 = (size_t)r * 512 + ((col0 + 4 * e) >> 1);
                    reinterpret_cast<__nv_bfloat162*>(OH)[o2]     = __nv_bfloat162{h0, h1};
                    reinterpret_cast<__nv_bfloat162*>(OH)[o2 + 1] = __nv_bfloat162{h2, h3};
                    reinterpret_cast<__nv_bfloat162*>(OL)[o2]     = __nv_bfloat162{l0, l1};
                    reinterpret_cast<__nv_bfloat162*>(OL)[o2 + 1] = __nv_bfloat162{l2, l3};
                } else if (EPI == 0) {
                    *reinterpret_cast<float4*>(O0 + (size_t)r * 1024 + (col0 - 1024) + 4 * e) = o;
                } else if (EPI == 1) {
                    *reinterpret_cast<float4*>(O0 + (size_t)r * 128 + col0 + 4 * e) = o;
                } else {   // EPI 3
                    *reinterpret_cast<float4*>(O0 + (size_t)r * 1024 + col0 + 4 * e) = o;
                }
            }
        }
        if (EPI == 2)
            atomicMax(reinterpret_cast<unsigned int*>(gmaxO + r), __float_as_uint(rowmax));
    }
    __syncthreads();
    if (tid == 0) { MBAR_INVAL(sb + 8); MBAR_INVAL(sb + 16); }
    __syncthreads();
    if (wid == 0) { TC_RELINQ(); TC_DEALLOC(tmem, 128); }
#endif  // TC_OK
}

// ============================ host ============================
extern "C" void kernel_launch(void* const* d_in, const int* in_sizes, int n_in,
                              void* d_out, int out_size)
{
    const float* x        = (const float*)d_in[0];
    const float* attn_W   = (const float*)d_in[1];
    const float* attn_b   = (const float*)d_in[2];
    const float* freq_W   = (const float*)d_in[3];
    const float* freq_b   = (const float*)d_in[4];
    const float* out_W    = (const float*)d_in[5];
    const float* out_b    = (const float*)d_in[6];
    const float* proj_W   = (const float*)d_in[7];
    const float* proj_b   = (const float*)d_in[8];
    const float* identity = (const float*)d_in[9];
    float* out = (float*)d_out;

    cudaFuncSetAttribute(tc_gemm<0>, cudaFuncAttributeMaxDynamicSharedMemorySize, SMEMSZ);
    cudaFuncSetAttribute(tc_gemm<1>, cudaFuncAttributeMaxDynamicSharedMemorySize, SMEMSZ);
    cudaFuncSetAttribute(tc_gemm<2>, cudaFuncAttributeMaxDynamicSharedMemorySize, SMEMSZ);
    cudaFuncSetAttribute(tc_gemm<3>, cudaFuncAttributeMaxDynamicSharedMemorySize, SMEMSZ);

    __nv_bfloat16 *zh[2], *zl[2], *xhi, *xlo, *schi, *sclo;
    __nv_bfloat16 *aWhi, *aWlo, *cWhi, *cWlo, *oWhi, *oWlo, *pWhi, *pWlo;
    float *v, *G, *gmax;
    cudaGetSymbolAddress((void**)&zh[0], g_zhi0); cudaGetSymbolAddress((void**)&zl[0], g_zlo0);
    cudaGetSymbolAddress((void**)&zh[1], g_zhi1); cudaGetSymbolAddress((void**)&zl[1], g_zlo1);
    cudaGetSymbolAddress((void**)&xhi, g_xhi);    cudaGetSymbolAddress((void**)&xlo, g_xlo);
    cudaGetSymbolAddress((void**)&schi, g_schi);  cudaGetSymbolAddress((void**)&sclo, g_sclo);
    cudaGetSymbolAddress((void**)&aWhi, g_aWhi);  cudaGetSymbolAddress((void**)&aWlo, g_aWlo);
    cudaGetSymbolAddress((void**)&cWhi, g_cWhi);  cudaGetSymbolAddress((void**)&cWlo, g_cWlo);
    cudaGetSymbolAddress((void**)&oWhi, g_oWhi);  cudaGetSymbolAddress((void**)&oWlo, g_oWlo);
    cudaGetSymbolAddress((void**)&pWhi, g_pWhi);  cudaGetSymbolAddress((void**)&pWlo, g_pWlo);
    cudaGetSymbolAddress((void**)&v, g_v);
    cudaGetSymbolAddress((void**)&G, g_G);
    cudaGetSymbolAddress((void**)&gmax, g_gmax);

    // ---- prep ----
    zero_gmax_kernel<<<(11 * Md + 1023) / 1024, 1024>>>();
    tsplit_kernel<<<(2048 * 1024 + 255) / 256, 256>>>(attn_W, aWhi, aWlo, 1024, 2048);
    tsplit_wcat_kernel<<<(128 * 1024 + 255) / 256, 256>>>(freq_W);
    tsplit_kernel<<<(1024 * 128 + 255) / 256, 256>>>(out_W, oWhi, oWlo, 128, 1024);
    tsplit_kernel<<<(1024 * 1024 + 255) / 256, 256>>>(proj_W, pWhi, pWlo, 1024, 1024);
    idw1_kernel<<<1, 256>>>(identity, freq_W);
    splitx_kernel<<<(int)(((size_t)Md * Cv / 4 + 255) / 256), 256>>>(x, xhi, xlo, (size_t)Md * Cv / 4);

    // ---- attn: [q|v] = x @ attn_W + attn_b; q split -> z[0], v fp32 ----
    tc_gemm<0><<<dim3(16, 128), 256, SMEMSZ>>>(xhi, xlo, aWhi, aWlo, attn_b,
                                               v, zh[0], zl[0], nullptr, 1024);

    // ---- scan ----
    int p = 0;
    for (int it = 0, n = 1; n < Tv; n <<= 1, it++) {
        const float* gmax_prev = (it == 0) ? nullptr : gmax + (size_t)(it - 1) * Md;
        tc_gemm<1><<<dim3(1, 128), 256, SMEMSZ>>>(zh[p], zl[p], cWhi, cWlo, nullptr,
                                                  G, nullptr, nullptr, nullptr, 1024);
        fuse_kernel<<<Md / 8, 256>>>(G, gmax_prev, freq_b, schi, sclo, n);
        tc_gemm<2><<<dim3(8, 128), 256, SMEMSZ>>>(schi, sclo, oWhi, oWlo, out_b,
                                                  nullptr, zh[1 - p], zl[1 - p],
                                                  gmax + (size_t)it * Md, 128);
        p ^= 1;
    }

    // ---- proj: out = (z*s*v) @ proj_W + proj_b ----
    mulv_split_kernel<<<Md, 256>>>(zh[p], zl[p], v, gmax + (size_t)10 * Md,
                                   zh[1 - p], zl[1 - p]);
    tc_gemm<3><<<dim3(8, 128), 256, SMEMSZ>>>(zh[1 - p], zl[1 - p], pWhi, pWlo, proj_b,
                                              out, nullptr, nullptr, nullptr, 1024);
}

// round 14
// speedup vs baseline: 3.6081x; 1.4521x over previous
#include <cuda_runtime.h>
#include <cuda_bf16.h>
#include <math.h>
#include <stdint.h>

constexpr int Tv = 2048, Cv = 1024, Md = 16384;
constexpr float EPS = 1e-6f;
constexpr int SMEMSZ = 1024 + 2 * 65536;   // header + 2 bufs x 4 tiles x 16KB

#if defined(__CUDA_ARCH_FEAT_SM103_ALL) || defined(__CUDA_ARCH_SPECIFIC__) || defined(__CUDA_ARCH_FAMILY_SPECIFIC__)
#define TC_OK 1
#else
#define TC_OK 0
#endif

// ---------------- device-global scratch ----------------
__device__ __nv_bfloat16 g_zhi0[(size_t)Md * Cv], g_zlo0[(size_t)Md * Cv];
__device__ __nv_bfloat16 g_zhi1[(size_t)Md * Cv], g_zlo1[(size_t)Md * Cv];
__device__ __nv_bfloat16 g_xhi[(size_t)Md * Cv],  g_xlo[(size_t)Md * Cv];
__device__ float g_v[(size_t)Md * Cv];
__device__ float g_G[(size_t)Md * 128];
__device__ float g_gmax[11 * Md];
__device__ float g_idW1[64];
__device__ float g_M[128 * 128];                   // out_W @ Wcat (fp32)
__device__ float g_bias[1152];                     // [out_b | cb]
__device__ __nv_bfloat16 g_schi[(size_t)Md * 128], g_sclo[(size_t)Md * 128];
__device__ __nv_bfloat16 g_aWhi[(size_t)2048 * 1024], g_aWlo[(size_t)2048 * 1024];
__device__ __nv_bfloat16 g_cWhi[(size_t)128 * 1024],  g_cWlo[(size_t)128 * 1024];   // Wcat^T [n=128][k=1024]
__device__ __nv_bfloat16 g_bWhi[(size_t)1152 * 128],  g_bWlo[(size_t)1152 * 128];   // [out_W^T | M^T] [n][k=128]
__device__ __nv_bfloat16 g_oAhi[(size_t)128 * 1024],  g_oAlo[(size_t)128 * 1024];   // out_W row-major split
__device__ __nv_bfloat16 g_pWhi[(size_t)1024 * 1024], g_pWlo[(size_t)1024 * 1024];

// ---------------- helpers ----------------
__device__ __forceinline__ void split1(float x, __nv_bfloat16& h, __nv_bfloat16& l) {
    h = __float2bfloat16_rn(x);
    l = __float2bfloat16_rn(x - __bfloat162float(h));
}

// ---------------- prep kernels ----------------
__global__ void tsplit_kernel(const float* __restrict__ W, __nv_bfloat16* __restrict__ hi,
                              __nv_bfloat16* __restrict__ lo, int K, int N) {
    size_t i = (size_t)blockIdx.x * 256 + threadIdx.x;
    if (i >= (size_t)K * N) return;
    int n = (int)(i / K), k = (int)(i % K);
    split1(W[(size_t)k * N + n], hi[i], lo[i]);
}
__global__ void tsplit_wcat_kernel(const float* __restrict__ freq_W) {
    size_t i = (size_t)blockIdx.x * 256 + threadIdx.x;
    if (i >= (size_t)128 * 1024) return;
    int n = (int)(i / 1024), k = (int)(i % 1024);
    float w = (n < 64) ? freq_W[(size_t)k * 64 + n] : freq_W[(size_t)(1024 + k) * 64 + (n - 64)];
    split1(w, g_cWhi[i], g_cWlo[i]);
}
__global__ void splitx_kernel(const float* __restrict__ X, __nv_bfloat16* __restrict__ hi,
                              __nv_bfloat16* __restrict__ lo, size_t n4) {
    size_t i = (size_t)blockIdx.x * 256 + threadIdx.x;
    if (i >= n4) return;
    float4 x = reinterpret_cast<const float4*>(X)[i];
    __nv_bfloat16 h[4], l[4];
    split1(x.x, h[0], l[0]); split1(x.y, h[1], l[1]);
    split1(x.z, h[2], l[2]); split1(x.w, h[3], l[3]);
    reinterpret_cast<__nv_bfloat162*>(hi)[2 * i]     = __nv_bfloat162{h[0], h[1]};
    reinterpret_cast<__nv_bfloat162*>(hi)[2 * i + 1] = __nv_bfloat162{h[2], h[3]};
    reinterpret_cast<__nv_bfloat162*>(lo)[2 * i]     = __nv_bfloat162{l[0], l[1]};
    reinterpret_cast<__nv_bfloat162*>(lo)[2 * i + 1] = __nv_bfloat162{l[2], l[3]};
}
__global__ void zero_gmax_kernel() {
    int i = blockIdx.x * 1024 + threadIdx.x;
    if (i < 11 * Md) g_gmax[i] = 0.f;
}
// out[n] = sum_{k<1024} vec[k] * W[k*64+n],  n<64
__global__ void vecw_kernel(const float* __restrict__ vec, const float* __restrict__ W,
                            float* __restrict__ out) {
    int tid = threadIdx.x, nn = tid & 63, part = tid >> 6;
    float acc = 0.f;
    for (int k = part * 256; k < part * 256 + 256; k++)
        acc += vec[k] * W[(size_t)k * 64 + nn];
    __shared__ float red[256];
    red[tid] = acc;
    __syncthreads();
    if (tid < 64) out[tid] = red[tid] + red[tid + 64] + red[tid + 128] + red[tid + 192];
}
__global__ void copyb_kernel(const float* __restrict__ out_b) {
    int i = blockIdx.x * 256 + threadIdx.x;
    if (i < 1024) g_bias[i] = out_b[i];
}
// fuse: f = s_prev*G1[r-n] + s_cur*G2[r] + freq_b; sc = split(sincos(f)). 8 rows/block.
__global__ void __launch_bounds__(256)
fuse_kernel(const float* __restrict__ G, const float* __restrict__ gmax_prev,
            const float* __restrict__ freq_b,
            __nv_bfloat16* __restrict__ SH, __nv_bfloat16* __restrict__ SL, int n) {
    int tid = threadIdx.x;
    int r = blockIdx.x * 8 + (tid >> 5), lane = tid & 31;
    int t = r & (Tv - 1);
    float scur = gmax_prev ? 1.f / (gmax_prev[r] + EPS) : 1.f;
    float2 g2 = *reinterpret_cast<const float2*>(G + (size_t)r * 128 + 64 + 2 * lane);
    float2 g1; float sp;
    if (t >= n) {
        g1 = *reinterpret_cast<const float2*>(G + (size_t)(r - n) * 128 + 2 * lane);
        sp = gmax_prev ? 1.f / (gmax_prev[r - n] + EPS) : 1.f;
    } else {
        g1 = *reinterpret_cast<const float2*>(g_idW1 + 2 * lane);
        sp = 1.f;
    }
    float2 fb = *reinterpret_cast<const float2*>(freq_b + 2 * lane);
    float f0 = sp * g1.x + scur * g2.x + fb.x;
    float f1 = sp * g1.y + scur * g2.y + fb.y;
    float s0, c0, s1, c1;
    sincosf(f0, &s0, &c0);
    sincosf(f1, &s1, &c1);
    __nv_bfloat16 hs0, ls0, hs1, ls1, hc0, lc0, hc1, lc1;
    split1(s0, hs0, ls0); split1(s1, hs1, ls1);
    split1(c0, hc0, lc0); split1(c1, hc1, lc1);
    size_t base = (size_t)r * 64 + lane;
    reinterpret_cast<__nv_bfloat162*>(SH)[base]      = __nv_bfloat162{hs0, hs1};
    reinterpret_cast<__nv_bfloat162*>(SL)[base]      = __nv_bfloat162{ls0, ls1};
    reinterpret_cast<__nv_bfloat162*>(SH)[base + 32] = __nv_bfloat162{hc0, hc1};
    reinterpret_cast<__nv_bfloat162*>(SL)[base + 32] = __nv_bfloat162{lc0, lc1};
}
// y = (zhi+zlo) * s * v -> split
__global__ void __launch_bounds__(256)
mulv_split_kernel(const __nv_bfloat16* __restrict__ ZH, const __nv_bfloat16* __restrict__ ZL,
                  const float* __restrict__ v, const float* __restrict__ gmax,
                  __nv_bfloat16* __restrict__ YH, __nv_bfloat16* __restrict__ YL) {
    int r = blockIdx.x, tid = threadIdx.x;
    float s = 1.f / (gmax[r] + EPS);
    __nv_bfloat162 h0 = reinterpret_cast<const __nv_bfloat162*>(ZH)[(size_t)r * 512 + 2 * tid];
    __nv_bfloat162 h1 = reinterpret_cast<const __nv_bfloat162*>(ZH)[(size_t)r * 512 + 2 * tid + 1];
    __nv_bfloat162 l0 = reinterpret_cast<const __nv_bfloat162*>(ZL)[(size_t)r * 512 + 2 * tid];
    __nv_bfloat162 l1 = reinterpret_cast<const __nv_bfloat162*>(ZL)[(size_t)r * 512 + 2 * tid + 1];
    float4 v4 = reinterpret_cast<const float4*>(v + (size_t)r * Cv)[tid];
    float y0 = (__bfloat162float(h0.x) + __bfloat162float(l0.x)) * s * v4.x;
    float y1 = (__bfloat162float(h0.y) + __bfloat162float(l0.y)) * s * v4.y;
    float y2 = (__bfloat162float(h1.x) + __bfloat162float(l1.x)) * s * v4.z;
    float y3 = (__bfloat162float(h1.y) + __bfloat162float(l1.y)) * s * v4.w;
    __nv_bfloat16 h[4], l[4];
    split1(y0, h[0], l[0]); split1(y1, h[1], l[1]);
    split1(y2, h[2], l[2]); split1(y3, h[3], l[3]);
    reinterpret_cast<__nv_bfloat162*>(YH)[(size_t)r * 512 + 2 * tid]     = __nv_bfloat162{h[0], h[1]};
    reinterpret_cast<__nv_bfloat162*>(YH)[(size_t)r * 512 + 2 * tid + 1] = __nv_bfloat162{h[2], h[3]};
    reinterpret_cast<__nv_bfloat162*>(YL)[(size_t)r * 512 + 2 * tid]     = __nv_bfloat162{l[0], l[1]};
    reinterpret_cast<__nv_bfloat162*>(YL)[(size_t)r * 512 + 2 * tid + 1] = __nv_bfloat162{l[2], l[3]};
}

#if TC_OK
__device__ __forceinline__ uint32_t smem_u32(const void* p) {
    uint32_t a;
    asm("{ .reg .u64 t; cvta.to.shared.u64 t, %1; cvt.u32.u64 %0, t; }" : "=r"(a) : "l"(p));
    return a;
}
__device__ __forceinline__ bool elect1() {
    uint32_t p;
    asm volatile("{\n\t.reg .pred p;\n\telect.sync _|p, 0xFFFFFFFF;\n\tselp.b32 %0,1,0,p;\n\t}" : "=r"(p));
    return p != 0;
}
#define SWZ(o) ((o) ^ (((o) >> 3) & 0x70))
__device__ __forceinline__ uint64_t mkdesc(uint32_t a) {
    const uint64_t base = (uint64_t(2) << 61) | (uint64_t(1) << 46) | (uint64_t(64) << 32) | (uint64_t(1) << 16);
    return base | ((uint64_t)(a >> 4) & 0x3FFF);
}
#define MBAR_INIT(mb, c) asm volatile("mbarrier.init.shared.b64 [%0], %1;" :: "r"(mb), "r"((uint32_t)(c)) : "memory")
#define MBAR_INVAL(mb)   asm volatile("mbarrier.inval.shared.b64 [%0];" :: "r"(mb) : "memory")
__device__ __forceinline__ void mbar_wait(uint32_t mb, uint32_t ph) {
    uint32_t done;
    asm volatile("{\n\t.reg .pred p;\n\tmbarrier.try_wait.parity.acquire.cta.shared::cta.b64 p, [%1], %2;\n\tselp.b32 %0,1,0,p;\n\t}"
                 : "=r"(done) : "r"(mb), "r"(ph) : "memory");
    if (!done)
        asm volatile("{\n\t.reg .pred P1;\nWL_%=:\n\tmbarrier.try_wait.parity.acquire.cta.shared::cta.b64 P1, [%0], %1, 0x989680;\n\t@P1 bra.uni WD_%=;\n\tbra.uni WL_%=;\nWD_%=:\n\t}"
                     :: "r"(mb), "r"(ph) : "memory");
}
#define TC_ALLOC(sm, n)  asm volatile("tcgen05.alloc.cta_group::1.sync.aligned.shared::cta.b32 [%0], %1;" :: "r"(sm), "r"((uint32_t)(n)) : "memory")
#define TC_DEALLOC(t, n) asm volatile("tcgen05.dealloc.cta_group::1.sync.aligned.b32 %0, %1;" :: "r"(t), "r"((uint32_t)(n)))
#define TC_RELINQ()      asm volatile("tcgen05.relinquish_alloc_permit.cta_group::1.sync.aligned;")
#define TC_COMMIT(mb)    asm volatile("tcgen05.commit.cta_group::1.mbarrier::arrive::one.shared::cluster.b64 [%0];" :: "r"(mb) : "memory")
#define TC_FENCE_AFTER() asm volatile("tcgen05.fence::after_thread_sync;" ::: "memory")
#define TC_WAIT_LD()     asm volatile("tcgen05.wait::ld.sync.aligned;" ::: "memory")
#define FENCE_ASYNC()    asm volatile("fence.proxy.async.shared::cta;" ::: "memory")
__device__ __forceinline__ void tc_mma(uint32_t d, uint64_t ad, uint64_t bd, uint32_t idesc, uint32_t en) {
    asm volatile("{\n\t.reg .pred p;\n\tsetp.ne.u32 p, %5, 0;\n\t"
                 "tcgen05.mma.cta_group::1.kind::f16 [%0], %1, %2, %3, {%4,%4,%4,%4}, p;\n\t}"
                 :: "r"(d), "l"(ad), "l"(bd), "r"(idesc), "r"(0u), "r"(en) : "memory");
}
#define TC_LD_X32(r, tm) \
    asm volatile("tcgen05.ld.sync.aligned.32x32b.x32.b32 " \
        "{%0,%1,%2,%3,%4,%5,%6,%7,%8,%9,%10,%11,%12,%13,%14,%15," \
        "%16,%17,%18,%19,%20,%21,%22,%23,%24,%25,%26,%27,%28,%29,%30,%31}, [%32];" \
        : "=r"((r)[0]),"=r"((r)[1]),"=r"((r)[2]),"=r"((r)[3]),"=r"((r)[4]),"=r"((r)[5]),"=r"((r)[6]),"=r"((r)[7]), \
          "=r"((r)[8]),"=r"((r)[9]),"=r"((r)[10]),"=r"((r)[11]),"=r"((r)[12]),"=r"((r)[13]),"=r"((r)[14]),"=r"((r)[15]), \
          "=r"((r)[16]),"=r"((r)[17]),"=r"((r)[18]),"=r"((r)[19]),"=r"((r)[20]),"=r"((r)[21]),"=r"((r)[22]),"=r"((r)[23]), \
          "=r"((r)[24]),"=r"((r)[25]),"=r"((r)[26]),"=r"((r)[27]),"=r"((r)[28]),"=r"((r)[29]),"=r"((r)[30]),"=r"((r)[31]) \
        : "r"(tm))
constexpr uint32_t IDESC128 = 0x8200490u;   // M=128, N=128
#endif  // TC_OK

// ---------------------------------------------------------------------------
// Unified tcgen05 GEMM (all A presplit bf16 hi/lo; pure-copy loads).
// EPI 0 attn : K=1024, N over 2048; q cols -> split OH/OL, v -> fp32 O0
// EPI 1 Gfp32: K=Kdim, N=128; fp32 store (no bias)  [initial G0 and M precompute]
// EPI 3 proj : K=1024, N=1024; +bias -> fp32 O0
// EPI 4 scan : K=128, N=1152 = [z'(rowmax, opt split) | G' fp32]; bias = g_bias
// ---------------------------------------------------------------------------
template<int EPI>
__global__ void __launch_bounds__(256) __cluster_dims__(1, 1, 1)
tc_gemm(const __nv_bfloat16* __restrict__ Ahi, const __nv_bfloat16* __restrict__ Alo,
        const __nv_bfloat16* __restrict__ Bhi, const __nv_bfloat16* __restrict__ Blo,
        const float* __restrict__ bias,
        float* __restrict__ O0, float* __restrict__ G,
        __nv_bfloat16* __restrict__ OH, __nv_bfloat16* __restrict__ OL,
        float* __restrict__ gmaxO, int Kdim)
{
#if TC_OK
    extern __shared__ char sm[];
    const uint32_t sb = smem_u32(sm);
    const int tid = threadIdx.x, wid = tid >> 5, lane = tid & 31;
    const int bm = blockIdx.y * 128, bn = blockIdx.x * 128;
    const int KT = Kdim >> 6;

    if (wid == 0) TC_ALLOC(sb + 0, 128);
    if (tid == 0) { MBAR_INIT(sb + 8, 1); MBAR_INIT(sb + 16, 1); }
    __syncthreads();
    uint32_t tmem;
    asm volatile("ld.shared.b32 %0, [%1];" : "=r"(tmem) : "r"(sb + 0));

    const int arow = tid >> 1, ah = tid & 1;
    int ph[2] = {0, 0};
#pragma unroll 1
    for (int kt = 0; kt < KT; kt++) {
        const int b = kt & 1;
        if (kt >= 2) { mbar_wait(sb + 8 + 8 * b, ph[b]); ph[b] ^= 1; }
        char* tb = sm + 1024 + b * 65536;
        const int k0 = kt * 64;
        {
            const __nv_bfloat16* sh = Ahi + (size_t)(bm + arow) * Kdim + k0 + 32 * ah;
            const __nv_bfloat16* sl = Alo + (size_t)(bm + arow) * Kdim + k0 + 32 * ah;
#pragma unroll
            for (int j = 0; j < 4; j++) {
                int off = arow * 128 + (32 * ah + 8 * j) * 2;
                *reinterpret_cast<uint4*>(tb + SWZ(off))         = reinterpret_cast<const uint4*>(sh)[j];
                *reinterpret_cast<uint4*>(tb + 16384 + SWZ(off)) = reinterpret_cast<const uint4*>(sl)[j];
            }
        }
        {
            const __nv_bfloat16* bh = Bhi + (size_t)(bn + arow) * Kdim + k0 + 32 * ah;
            const __nv_bfloat16* bl = Blo + (size_t)(bn + arow) * Kdim + k0 + 32 * ah;
#pragma unroll
            for (int j = 0; j < 4; j++) {
                int off = arow * 128 + (32 * ah + 8 * j) * 2;
                *reinterpret_cast<uint4*>(tb + 32768 + SWZ(off)) = reinterpret_cast<const uint4*>(bh)[j];
                *reinterpret_cast<uint4*>(tb + 49152 + SWZ(off)) = reinterpret_cast<const uint4*>(bl)[j];
            }
        }
        FENCE_ASYNC();
        __syncthreads();
        if (wid == 0 && elect1()) {
            uint32_t base = sb + 1024 + b * 65536;
            uint64_t dAh = mkdesc(base), dAl = mkdesc(base + 16384);
            uint64_t dBh = mkdesc(base + 32768), dBl = mkdesc(base + 49152);
#pragma unroll
            for (int s2 = 0; s2 < 4; s2++) {
                tc_mma(tmem, dAh + 2 * s2, dBh + 2 * s2, IDESC128, (kt == 0 && s2 == 0) ? 0u : 1u);
                tc_mma(tmem, dAh + 2 * s2, dBl + 2 * s2, IDESC128, 1u);
                tc_mma(tmem, dAl + 2 * s2, dBh + 2 * s2, IDESC128, 1u);
            }
            TC_COMMIT(sb + 8 + 8 * b);
        }
    }
    { const int bl = (KT - 1) & 1; mbar_wait(sb + 8 + 8 * bl, ph[bl]); }
    TC_FENCE_AFTER();

    if (wid < 4) {
        const int r = bm + wid * 32 + lane;
        float rowmax = 0.f;
#pragma unroll 1
        for (int c4 = 0; c4 < 4; c4++) {
            uint32_t regs[32];
            TC_LD_X32(regs, tmem + 32 * c4);
            TC_WAIT_LD();
            const int col0 = bn + 32 * c4;
#pragma unroll
            for (int e = 0; e < 8; e++) {
                float4 o;
                o.x = __uint_as_float(regs[4 * e + 0]);
                o.y = __uint_as_float(regs[4 * e + 1]);
                o.z = __uint_as_float(regs[4 * e + 2]);
                o.w = __uint_as_float(regs[4 * e + 3]);
                if (EPI != 1) {
                    o.x += bias[col0 + 4 * e + 0]; o.y += bias[col0 + 4 * e + 1];
                    o.z += bias[col0 + 4 * e + 2]; o.w += bias[col0 + 4 * e + 3];
                }
                if (EPI == 0) {
                    if (col0 < 1024) {
                        __nv_bfloat16 h0, l0, h1, l1, h2, l2, h3, l3;
                        split1(o.x, h0, l0); split1(o.y, h1, l1);
                        split1(o.z, h2, l2); split1(o.w, h3, l3);
                        size_t o2 = (size_t)r * 512 + ((col0 + 4 * e) >> 1);
                        reinterpret_cast<__nv_bfloat162*>(OH)[o2]     = __nv_bfloat162{h0, h1};
                        reinterpret_cast<__nv_bfloat162*>(OH)[o2 + 1] = __nv_bfloat162{h2, h3};
                        reinterpret_cast<__nv_bfloat162*>(OL)[o2]     = __nv_bfloat162{l0, l1};
                        reinterpret_cast<__nv_bfloat162*>(OL)[o2 + 1] = __nv_bfloat162{l2, l3};
                    } else {
                        *reinterpret_cast<float4*>(O0 + (size_t)r * 1024 + (col0 - 1024) + 4 * e) = o;
                    }
                } else if (EPI == 1) {
                    *reinterpret_cast<float4*>(O0 + (size_t)r * 128 + col0 + 4 * e) = o;
                } else if (EPI == 3) {
                    *reinterpret_cast<float4*>(O0 + (size_t)r * 1024 + col0 + 4 * e) = o;
                } else {   // EPI 4
                    if (col0 < 1024) {
                        rowmax = fmaxf(rowmax,
                                 fmaxf(fmaxf(fabsf(o.x), fabsf(o.y)), fmaxf(fabsf(o.z), fabsf(o.w))));
                        if (OH) {
                            __nv_bfloat16 h0, l0, h1, l1, h2, l2, h3, l3;
                            split1(o.x, h0, l0); split1(o.y, h1, l1);
                            split1(o.z, h2, l2); split1(o.w, h3, l3);
                            size_t o2 = (size_t)r * 512 + ((col0 + 4 * e) >> 1);
                            reinterpret_cast<__nv_bfloat162*>(OH)[o2]     = __nv_bfloat162{h0, h1};
                            reinterpret_cast<__nv_bfloat162*>(OH)[o2 + 1] = __nv_bfloat162{h2, h3};
                            reinterpret_cast<__nv_bfloat162*>(OL)[o2]     = __nv_bfloat162{l0, l1};
                            reinterpret_cast<__nv_bfloat162*>(OL)[o2 + 1] = __nv_bfloat162{l2, l3};
                        }
                    } else {
                        *reinterpret_cast<float4*>(G + (size_t)r * 128 + (col0 - 1024) + 4 * e) = o;
                    }
                }
            }
        }
        if (EPI == 4 && bn < 1024)
            atomicMax(reinterpret_cast<unsigned int*>(gmaxO + r), __float_as_uint(rowmax));
    }
    __syncthreads();
    if (tid == 0) { MBAR_INVAL(sb + 8); MBAR_INVAL(sb + 16); }
    __syncthreads();
    if (wid == 0) { TC_RELINQ(); TC_DEALLOC(tmem, 128); }
#endif  // TC_OK
}

// ============================ host ============================
extern "C" void kernel_launch(void* const* d_in, const int* in_sizes, int n_in,
                              void* d_out, int out_size)
{
    const float* x        = (const float*)d_in[0];
    const float* attn_W   = (const float*)d_in[1];
    const float* attn_b   = (const float*)d_in[2];
    const float* freq_W   = (const float*)d_in[3];
    const float* freq_b   = (const float*)d_in[4];
    const float* out_W    = (const float*)d_in[5];
    const float* out_b    = (const float*)d_in[6];
    const float* proj_W   = (const float*)d_in[7];
    const float* proj_b   = (const float*)d_in[8];
    const float* identity = (const float*)d_in[9];
    float* out = (float*)d_out;

    cudaFuncSetAttribute(tc_gemm<0>, cudaFuncAttributeMaxDynamicSharedMemorySize, SMEMSZ);
    cudaFuncSetAttribute(tc_gemm<1>, cudaFuncAttributeMaxDynamicSharedMemorySize, SMEMSZ);
    cudaFuncSetAttribute(tc_gemm<3>, cudaFuncAttributeMaxDynamicSharedMemorySize, SMEMSZ);
    cudaFuncSetAttribute(tc_gemm<4>, cudaFuncAttributeMaxDynamicSharedMemorySize, SMEMSZ);

    __nv_bfloat16 *zh[2], *zl[2], *xhi, *xlo, *schi, *sclo;
    __nv_bfloat16 *aWhi, *aWlo, *cWhi, *cWlo, *bWhi, *bWlo, *oAhi, *oAlo, *pWhi, *pWlo;
    float *v, *G, *gmax, *Mbuf, *biasbuf, *idW1;
    cudaGetSymbolAddress((void**)&zh[0], g_zhi0); cudaGetSymbolAddress((void**)&zl[0], g_zlo0);
    cudaGetSymbolAddress((void**)&zh[1], g_zhi1); cudaGetSymbolAddress((void**)&zl[1], g_zlo1);
    cudaGetSymbolAddress((void**)&xhi, g_xhi);    cudaGetSymbolAddress((void**)&xlo, g_xlo);
    cudaGetSymbolAddress((void**)&schi, g_schi);  cudaGetSymbolAddress((void**)&sclo, g_sclo);
    cudaGetSymbolAddress((void**)&aWhi, g_aWhi);  cudaGetSymbolAddress((void**)&aWlo, g_aWlo);
    cudaGetSymbolAddress((void**)&cWhi, g_cWhi);  cudaGetSymbolAddress((void**)&cWlo, g_cWlo);
    cudaGetSymbolAddress((void**)&bWhi, g_bWhi);  cudaGetSymbolAddress((void**)&bWlo, g_bWlo);
    cudaGetSymbolAddress((void**)&oAhi, g_oAhi);  cudaGetSymbolAddress((void**)&oAlo, g_oAlo);
    cudaGetSymbolAddress((void**)&pWhi, g_pWhi);  cudaGetSymbolAddress((void**)&pWlo, g_pWlo);
    cudaGetSymbolAddress((void**)&v, g_v);
    cudaGetSymbolAddress((void**)&G, g_G);
    cudaGetSymbolAddress((void**)&gmax, g_gmax);
    cudaGetSymbolAddress((void**)&Mbuf, g_M);
    cudaGetSymbolAddress((void**)&biasbuf, g_bias);
    cudaGetSymbolAddress((void**)&idW1, g_idW1);

    // ---- prep ----
    zero_gmax_kernel<<<(11 * Md + 1023) / 1024, 1024>>>();
    tsplit_kernel<<<(2048 * 1024 + 255) / 256, 256>>>(attn_W, aWhi, aWlo, 1024, 2048);
    tsplit_wcat_kernel<<<(128 * 1024 + 255) / 256, 256>>>(freq_W);
    tsplit_kernel<<<(1024 * 128 + 255) / 256, 256>>>(out_W, bWhi, bWlo, 128, 1024);  // B rows 0..1023
    tsplit_kernel<<<(1024 * 1024 + 255) / 256, 256>>>(proj_W, pWhi, pWlo, 1024, 1024);
    splitx_kernel<<<(128 * 1024 / 4 + 255) / 256, 256>>>(out_W, oAhi, oAlo, 128 * 1024 / 4);
    vecw_kernel<<<1, 256>>>(identity, freq_W, idW1);
    vecw_kernel<<<1, 256>>>(out_b, freq_W, biasbuf + 1024);              // cb[0:64]
    vecw_kernel<<<1, 256>>>(out_b, freq_W + 1024 * 64, biasbuf + 1088);  // cb[64:128]
    copyb_kernel<<<4, 256>>>(out_b);
    splitx_kernel<<<(int)(((size_t)Md * Cv / 4 + 255) / 256), 256>>>(x, xhi, xlo, (size_t)Md * Cv / 4);

    // M = out_W @ Wcat  (128x128, fp32), then split^T into B rows 1024..1151
    tc_gemm<1><<<dim3(1, 1), 256, SMEMSZ>>>(oAhi, oAlo, cWhi, cWlo, nullptr,
                                            Mbuf, nullptr, nullptr, nullptr, nullptr, 1024);
    tsplit_kernel<<<(128 * 128 + 255) / 256, 256>>>(Mbuf, bWhi + (size_t)1024 * 128,
                                                    bWlo + (size_t)1024 * 128, 128, 128);

    // attn: [q|v] = x @ attn_W + attn_b; q split -> z[0], v fp32
    tc_gemm<0><<<dim3(16, 128), 256, SMEMSZ>>>(xhi, xlo, aWhi, aWlo, attn_b,
                                               v, nullptr, zh[0], zl[0], nullptr, 1024);
    // initial G0 = z0 @ Wcat
    tc_gemm<1><<<dim3(1, 128), 256, SMEMSZ>>>(zh[0], zl[0], cWhi, cWlo, nullptr,
                                              G, nullptr, nullptr, nullptr, nullptr, 1024);

    // ---- scan: fuse + combined [z' | G'] GEMM per iteration ----
    for (int it = 0, n = 1; n < Tv; n <<= 1, it++) {
        const float* gmax_prev = (it == 0) ? nullptr : gmax + (size_t)(it - 1) * Md;
        fuse_kernel<<<Md / 8, 256>>>(G, gmax_prev, freq_b, schi, sclo, n);
        bool last = (n * 2 >= Tv);
        tc_gemm<4><<<dim3(9, 128), 256, SMEMSZ>>>(schi, sclo, bWhi, bWlo, biasbuf,
                                                  nullptr, G,
                                                  last ? zh[1] : nullptr, last ? zl[1] : nullptr,
                                                  gmax + (size_t)it * Md, 128);
    }

    // ---- proj: out = (z*s*v) @ proj_W + proj_b ----
    mulv_split_kernel<<<Md, 256>>>(zh[1], zl[1], v, gmax + (size_t)10 * Md, zh[0], zl[0]);
    tc_gemm<3><<<dim3(8, 128), 256, SMEMSZ>>>(zh[0], zl[0], pWhi, pWlo, proj_b,
                                              out, nullptr, nullptr, nullptr, nullptr, 1024);
}